// round 7
// baseline (speedup 1.0000x reference)
#include <cuda_runtime.h>
#include <cuda_bf16.h>
#include <math_constants.h>
#include <cstdint>

#define BATCH 4
#define SEQ   2048
#define DMODEL 1024
#define NHEADS 16
#define DHEAD 64
#define NEG_VAL (-32767.0f)
#define MTOT  (BATCH * SEQ)      // 8192
#define K3    (3 * DMODEL)       // 3072

typedef __nv_bfloat16 bf16;

// ---- global scratch (bf16 hi/lo split operands) ----
__device__ bf16 g_in_hi[(size_t)MTOT * K3];
__device__ bf16 g_in_lo[(size_t)MTOT * K3];
__device__ bf16 g_wqkv_hi[(size_t)K3 * K3];
__device__ bf16 g_wqkv_lo[(size_t)K3 * K3];
__device__ bf16 g_qkv_hi[(size_t)MTOT * K3];
__device__ bf16 g_qkv_lo[(size_t)MTOT * K3];
__device__ bf16 g_attn_hi[(size_t)MTOT * DMODEL];
__device__ bf16 g_attn_lo[(size_t)MTOT * DMODEL];
__device__ bf16 g_wout_hi[(size_t)DMODEL * DMODEL];
__device__ bf16 g_wout_lo[(size_t)DMODEL * DMODEL];

// ===========================================================================
// helpers
// ===========================================================================
__device__ __forceinline__ uint32_t smem_u32(const void* p) {
    uint32_t a;
    asm("{ .reg .u64 t; cvta.to.shared.u64 t, %1; cvt.u32.u64 %0, t; }"
        : "=r"(a) : "l"(p));
    return a;
}
__device__ __forceinline__ void ldm_x4(uint32_t* r, uint32_t addr) {
    asm volatile("ldmatrix.sync.aligned.m8n8.x4.shared.b16 {%0,%1,%2,%3}, [%4];"
                 : "=r"(r[0]), "=r"(r[1]), "=r"(r[2]), "=r"(r[3]) : "r"(addr));
}
__device__ __forceinline__ void ldm_x4t(uint32_t* r, uint32_t addr) {
    asm volatile("ldmatrix.sync.aligned.m8n8.x4.trans.shared.b16 {%0,%1,%2,%3}, [%4];"
                 : "=r"(r[0]), "=r"(r[1]), "=r"(r[2]), "=r"(r[3]) : "r"(addr));
}
__device__ __forceinline__ void mma_bf16(float* c, const uint32_t* a, const uint32_t* b) {
    asm volatile(
        "mma.sync.aligned.m16n8k16.row.col.f32.bf16.bf16.f32 "
        "{%0,%1,%2,%3}, {%4,%5,%6,%7}, {%8,%9}, {%0,%1,%2,%3};"
        : "+f"(c[0]), "+f"(c[1]), "+f"(c[2]), "+f"(c[3])
        : "r"(a[0]), "r"(a[1]), "r"(a[2]), "r"(a[3]), "r"(b[0]), "r"(b[1]));
}
__device__ __forceinline__ uint32_t packb(bf16 a, bf16 b) {
    uint16_t ua = *(uint16_t*)&a, ub = *(uint16_t*)&b;
    return (uint32_t)ua | ((uint32_t)ub << 16);
}
__device__ __forceinline__ void split4(float4 v, uint2& hi, uint2& lo) {
    bf16 hx = __float2bfloat16_rn(v.x);
    bf16 hy = __float2bfloat16_rn(v.y);
    bf16 hz = __float2bfloat16_rn(v.z);
    bf16 hw = __float2bfloat16_rn(v.w);
    bf16 lx = __float2bfloat16_rn(v.x - __bfloat162float(hx));
    bf16 ly = __float2bfloat16_rn(v.y - __bfloat162float(hy));
    bf16 lz = __float2bfloat16_rn(v.z - __bfloat162float(hz));
    bf16 lw = __float2bfloat16_rn(v.w - __bfloat162float(hw));
    hi.x = packb(hx, hy); hi.y = packb(hz, hw);
    lo.x = packb(lx, ly); lo.y = packb(lz, lw);
}
__device__ __forceinline__ void cp16(uint32_t s, const void* g) {
    asm volatile("cp.async.cg.shared.global [%0], [%1], 16;" :: "r"(s), "l"(g));
}

// ===========================================================================
// split kernels
// ===========================================================================
__global__ void __launch_bounds__(256) split_concat(
    const float* __restrict__ q, const float* __restrict__ k,
    const float* __restrict__ v, bf16* __restrict__ hi, bf16* __restrict__ lo)
{
    const int idx = blockIdx.x * 256 + threadIdx.x;        // float4 index
    const int row = idx / 768;
    const int rem = idx - row * 768;                        // 0..767
    const int seg = rem >> 8;
    const int cin = rem & 255;
    const float* src = (seg == 0) ? q : ((seg == 1) ? k : v);
    float4 val = *(const float4*)(src + (size_t)row * DMODEL + cin * 4);
    uint2 h, l;
    split4(val, h, l);
    const size_t de = (size_t)row * K3 + rem * 4;
    *(uint2*)(hi + de) = h;
    *(uint2*)(lo + de) = l;
}

__global__ void __launch_bounds__(256) split_plain(
    const float* __restrict__ src, bf16* __restrict__ hi, bf16* __restrict__ lo)
{
    const size_t idx = (size_t)(blockIdx.x * 256 + threadIdx.x) * 4;
    float4 val = *(const float4*)(src + idx);
    uint2 h, l;
    split4(val, h, l);
    *(uint2*)(hi + idx) = h;
    *(uint2*)(lo + idx) = l;
}

// ===========================================================================
// Pure-bf16 mma GEMM. BM=256, BN=128, BK=32, 512 threads (16 warps, warp
// tile 64x32), 1 CTA/SM, 3-stage cp.async pipeline, 1 barrier per k-iter.
// C = (Ahi+Alo) @ (Bhi+Blo)^T + bias, 3-product compensation.
// ===========================================================================
#define BMM 256
#define BNN 128
// stage layout in bf16 elements (row stride 40)
#define S_AHI 0
#define S_ALO 10240
#define S_BHI 20480
#define S_BLO 25600
#define S_ELEMS 30720
#define S_BYTES (S_ELEMS * 2)        // 61440
#define GEMM_SMEM (3 * S_BYTES)      // 184320

template <int OMODE>
__global__ void __launch_bounds__(512, 1) gemm_bf16(
    const bf16* __restrict__ Ahi, const bf16* __restrict__ Alo,
    const bf16* __restrict__ Bhi, const bf16* __restrict__ Blo,
    const float* __restrict__ bias,
    float* __restrict__ C, bf16* __restrict__ Chi, bf16* __restrict__ Clo,
    int M, int N, int K)
{
    extern __shared__ __align__(128) char smraw[];
    const uint32_t smb = smem_u32(smraw);
    const int tid = threadIdx.x, lane = tid & 31, wid = tid >> 5;
    const int wm = wid & 3, wn = wid >> 2;
    const int m0 = blockIdx.y * BMM, n0 = blockIdx.x * BNN;

    float acc[4][4][4];
#pragma unroll
    for (int i = 0; i < 4; i++)
#pragma unroll
        for (int j = 0; j < 4; j++)
#pragma unroll
            for (int e = 0; e < 4; e++) acc[i][j][e] = 0.f;

    const int nkt = K >> 5;

    // per-thread load slots: A (2 rows of 16B x2 for hi,lo), B (1 row of 16B)
    const int arow0 = tid >> 2;               // 0..127
    const int ac8   = (tid & 3) << 3;         // col (elem) 0,8,16,24
    const int brow  = tid >> 2;               // 0..127 (tid<512 -> use &511 trick)
    // A rows handled: arow0 and arow0+128 ; B rows: brow (only tids 0..511 -> 128 rows covered by tid>>2 in 0..127)

#define ISSUE_STAGE(sb_, k0_) do {                                            \
    const uint32_t _sb = (sb_);                                               \
    const int _k0 = (k0_);                                                    \
    /* A tile: 256 rows x 32 cols, hi+lo */                                   \
    {                                                                         \
        const size_t ga0 = (size_t)(m0 + arow0) * K + _k0 + ac8;              \
        const size_t ga1 = (size_t)(m0 + 128 + arow0) * K + _k0 + ac8;        \
        const uint32_t d0 = (uint32_t)(arow0 * 40 + ac8) * 2;                 \
        const uint32_t d1 = (uint32_t)((128 + arow0) * 40 + ac8) * 2;         \
        cp16(_sb + S_AHI * 2 + d0, Ahi + ga0);                                \
        cp16(_sb + S_AHI * 2 + d1, Ahi + ga1);                                \
        cp16(_sb + S_ALO * 2 + d0, Alo + ga0);                                \
        cp16(_sb + S_ALO * 2 + d1, Alo + ga1);                                \
    }                                                                         \
    /* B tile: 128 rows x 32 cols, hi+lo */                                   \
    {                                                                         \
        const size_t gb = (size_t)(n0 + brow) * K + _k0 + ac8;                \
        const uint32_t db = (uint32_t)(brow * 40 + ac8) * 2;                  \
        cp16(_sb + S_BHI * 2 + db, Bhi + gb);                                 \
        cp16(_sb + S_BLO * 2 + db, Blo + gb);                                 \
    }                                                                         \
} while (0)

    // prologue: stages 0 and 1
    ISSUE_STAGE(smb, 0);
    asm volatile("cp.async.commit_group;");
    ISSUE_STAGE(smb + S_BYTES, 32);
    asm volatile("cp.async.commit_group;");

    int cur = 0;
    for (int kt = 0; kt < nkt; kt++) {
        asm volatile("cp.async.wait_group 1;");
        __syncthreads();

        // prefetch kt+2 into the buffer freed at kt-1
        if (kt + 2 < nkt) {
            int nx = cur + 2; if (nx >= 3) nx -= 3;
            ISSUE_STAGE(smb + (uint32_t)nx * S_BYTES, (kt + 2) << 5);
        }
        asm volatile("cp.async.commit_group;");

        const uint32_t sb = smb + (uint32_t)cur * S_BYTES;
#pragma unroll
        for (int ks = 0; ks < 2; ks++) {
            uint32_t bh[2][4], bl[2][4];
#pragma unroll
            for (int p = 0; p < 2; p++) {
                const uint32_t row = (uint32_t)(wn * 32 + p * 16 + (lane & 7)
                                                + ((lane >> 4) & 1) * 8);
                const uint32_t kc = (uint32_t)(ks * 16 + ((lane >> 3) & 1) * 8);
                const uint32_t eo = (row * 40 + kc) * 2;
                ldm_x4(bh[p], sb + S_BHI * 2 + eo);
                ldm_x4(bl[p], sb + S_BLO * 2 + eo);
            }
#pragma unroll
            for (int mt = 0; mt < 4; mt++) {
                uint32_t ah[4], al[4];
                const uint32_t eo =
                    (uint32_t)((wm * 64 + mt * 16 + (lane & 15)) * 40
                               + ks * 16 + ((lane >> 4) & 1) * 8) * 2;
                ldm_x4(ah, sb + S_AHI * 2 + eo);
                ldm_x4(al, sb + S_ALO * 2 + eo);
#pragma unroll
                for (int p = 0; p < 2; p++)
#pragma unroll
                    for (int hf = 0; hf < 2; hf++) {
                        float* a = acc[mt][p * 2 + hf];
                        mma_bf16(a, ah, &bh[p][hf * 2]);
                        mma_bf16(a, al, &bh[p][hf * 2]);
                        mma_bf16(a, ah, &bl[p][hf * 2]);
                    }
            }
        }
        if (++cur == 3) cur = 0;
    }
#undef ISSUE_STAGE

    // epilogue
#pragma unroll
    for (int mt = 0; mt < 4; mt++) {
        const int rg = m0 + wm * 64 + mt * 16 + (lane >> 2);
#pragma unroll
        for (int nt = 0; nt < 4; nt++) {
            const int c = n0 + wn * 32 + nt * 8 + (lane & 3) * 2;
            const float b0 = bias[c], b1 = bias[c + 1];
            const float v00 = acc[mt][nt][0] + b0, v01 = acc[mt][nt][1] + b1;
            const float v10 = acc[mt][nt][2] + b0, v11 = acc[mt][nt][3] + b1;
            if (OMODE == 0) {
                *(float2*)(C + (size_t)rg * N + c)       = make_float2(v00, v01);
                *(float2*)(C + (size_t)(rg + 8) * N + c) = make_float2(v10, v11);
            } else {
                bf16 h00 = __float2bfloat16_rn(v00), h01 = __float2bfloat16_rn(v01);
                bf16 h10 = __float2bfloat16_rn(v10), h11 = __float2bfloat16_rn(v11);
                bf16 l00 = __float2bfloat16_rn(v00 - __bfloat162float(h00));
                bf16 l01 = __float2bfloat16_rn(v01 - __bfloat162float(h01));
                bf16 l10 = __float2bfloat16_rn(v10 - __bfloat162float(h10));
                bf16 l11 = __float2bfloat16_rn(v11 - __bfloat162float(h11));
                ((uint32_t*)Chi)[((size_t)rg * N + c) >> 1]       = packb(h00, h01);
                ((uint32_t*)Clo)[((size_t)rg * N + c) >> 1]       = packb(l00, l01);
                ((uint32_t*)Chi)[((size_t)(rg + 8) * N + c) >> 1] = packb(h10, h11);
                ((uint32_t*)Clo)[((size_t)(rg + 8) * N + c) >> 1] = packb(l10, l11);
            }
        }
    }
}

// ===========================================================================
// Tensor-core causal flash attention (unchanged from round 6).
// ===========================================================================
#define SQHI 0
#define SQLO 9216
#define KV0   18432
#define KVSTG 18432
#define OKHI 0
#define OKLO 4608
#define OVHI 9216
#define OVLO 13824
#define ATTN_SMEM ((18432 + 2 * 18432) * 2)   // 110592 bytes

__global__ void __launch_bounds__(256, 2) attn_mma(
    const bf16* __restrict__ qkv_hi, const bf16* __restrict__ qkv_lo,
    bf16* __restrict__ ohi, bf16* __restrict__ olo)
{
    extern __shared__ __align__(128) char smraw[];
    const uint32_t smb = smem_u32(smraw);
    const int tid = threadIdx.x, lane = tid & 31, wid = tid >> 5;
    const int gid = lane >> 2, tig = lane & 3;
    const int bt = blockIdx.x, h = blockIdx.y, b = blockIdx.z;
    const int g0 = bt * 128;
    const int jtmax = 2 * bt + 1;

    {
#pragma unroll
        for (int t = 0; t < 4; t++) {
            const int idx = tid + t * 256;
            const int row = idx >> 3;
            const int c8 = (idx & 7) * 8;
            const size_t g = ((size_t)b * SEQ + g0 + row) * K3 + h * 64 + c8;
            const uint32_t so = (uint32_t)(row * 72 + c8);
            cp16(smb + (SQHI + so) * 2, qkv_hi + g);
            cp16(smb + (SQLO + so) * 2, qkv_lo + g);
        }
#pragma unroll
        for (int t = 0; t < 2; t++) {
            const int idx = tid + t * 256;
            const int row = idx >> 3;
            const int c8 = (idx & 7) * 8;
            const size_t g = ((size_t)b * SEQ + row) * K3 + h * 64 + c8;
            const uint32_t so = KV0 + (uint32_t)(row * 72 + c8);
            cp16(smb + (so + OKHI) * 2, qkv_hi + g + DMODEL);
            cp16(smb + (so + OKLO) * 2, qkv_lo + g + DMODEL);
            cp16(smb + (so + OVHI) * 2, qkv_hi + g + 2 * DMODEL);
            cp16(smb + (so + OVLO) * 2, qkv_lo + g + 2 * DMODEL);
        }
        asm volatile("cp.async.commit_group;");
    }

    float oacc[8][4];
#pragma unroll
    for (int i = 0; i < 8; i++)
#pragma unroll
        for (int e = 0; e < 4; e++) oacc[i][e] = 0.f;
    float mA = -CUDART_INF_F, mB = -CUDART_INF_F, lA = 0.f, lB = 0.f;

    const int wrow = g0 + wid * 16;
    const int rA = wrow + gid;

    for (int jt = 0; jt <= jtmax; jt++) {
        if (jt + 1 <= jtmax) {
            const int j1 = (jt + 1) * 64;
            const uint32_t stg = KV0 + ((jt + 1) & 1) * KVSTG;
#pragma unroll
            for (int t = 0; t < 2; t++) {
                const int idx = tid + t * 256;
                const int row = idx >> 3;
                const int c8 = (idx & 7) * 8;
                const size_t g = ((size_t)b * SEQ + j1 + row) * K3 + h * 64 + c8;
                const uint32_t so = stg + (uint32_t)(row * 72 + c8);
                cp16(smb + (so + OKHI) * 2, qkv_hi + g + DMODEL);
                cp16(smb + (so + OKLO) * 2, qkv_lo + g + DMODEL);
                cp16(smb + (so + OVHI) * 2, qkv_hi + g + 2 * DMODEL);
                cp16(smb + (so + OVLO) * 2, qkv_lo + g + 2 * DMODEL);
            }
            asm volatile("cp.async.commit_group;");
            asm volatile("cp.async.wait_group 1;");
        } else {
            asm volatile("cp.async.wait_group 0;");
        }
        __syncthreads();

        const uint32_t kst = KV0 + (jt & 1) * KVSTG;
        const int j0 = jt * 64;

        float sacc[8][4];
#pragma unroll
        for (int i = 0; i < 8; i++)
#pragma unroll
            for (int e = 0; e < 4; e++) sacc[i][e] = 0.f;

#pragma unroll
        for (int ks = 0; ks < 4; ks++) {
            uint32_t ah[4], al[4];
            const uint32_t eo =
                (uint32_t)((wid * 16 + (lane & 15)) * 72
                           + ks * 16 + ((lane >> 4) & 1) * 8) * 2;
            ldm_x4(ah, smb + SQHI * 2 + eo);
            ldm_x4(al, smb + SQLO * 2 + eo);
#pragma unroll
            for (int pf = 0; pf < 4; pf++) {
                uint32_t bh[4], bl[4];
                const uint32_t row = (uint32_t)(pf * 16 + (lane & 7)
                                                + ((lane >> 4) & 1) * 8);
                const uint32_t kc = (uint32_t)(ks * 16 + ((lane >> 3) & 1) * 8);
                const uint32_t eb = (row * 72 + kc) * 2;
                ldm_x4(bh, smb + (kst + OKHI) * 2 + eb);
                ldm_x4(bl, smb + (kst + OKLO) * 2 + eb);
#pragma unroll
                for (int hf = 0; hf < 2; hf++) {
                    float* sa = sacc[pf * 2 + hf];
                    mma_bf16(sa, ah, &bh[hf * 2]);
                    mma_bf16(sa, al, &bh[hf * 2]);
                    mma_bf16(sa, ah, &bl[hf * 2]);
                }
            }
        }

        const bool needmask = (j0 + 63 > wrow);
#pragma unroll
        for (int nf = 0; nf < 8; nf++) {
#pragma unroll
            for (int e = 0; e < 4; e++) {
                float vsc = sacc[nf][e] * 8.0f;
                if (needmask) {
                    const int col = j0 + nf * 8 + tig * 2 + (e & 1);
                    const int row = (e < 2) ? rA : (rA + 8);
                    if (col > row) vsc = NEG_VAL;
                }
                sacc[nf][e] = vsc;
            }
        }

        float mxA = -CUDART_INF_F, mxB = -CUDART_INF_F;
#pragma unroll
        for (int nf = 0; nf < 8; nf++) {
            mxA = fmaxf(mxA, fmaxf(sacc[nf][0], sacc[nf][1]));
            mxB = fmaxf(mxB, fmaxf(sacc[nf][2], sacc[nf][3]));
        }
        mxA = fmaxf(mxA, __shfl_xor_sync(0xffffffffu, mxA, 1));
        mxA = fmaxf(mxA, __shfl_xor_sync(0xffffffffu, mxA, 2));
        mxB = fmaxf(mxB, __shfl_xor_sync(0xffffffffu, mxB, 1));
        mxB = fmaxf(mxB, __shfl_xor_sync(0xffffffffu, mxB, 2));

        const float mnA = fmaxf(mA, mxA), mnB = fmaxf(mB, mxB);
        const float alA = __expf(mA - mnA), alB = __expf(mB - mnB);

        float psA = 0.f, psB = 0.f;
        uint32_t phiA[8], phiB[8], ploA[8], ploB[8];
#pragma unroll
        for (int nf = 0; nf < 8; nf++) {
            const float p0 = __expf(sacc[nf][0] - mnA);
            const float p1 = __expf(sacc[nf][1] - mnA);
            const float p2 = __expf(sacc[nf][2] - mnB);
            const float p3 = __expf(sacc[nf][3] - mnB);
            psA += p0 + p1; psB += p2 + p3;
            bf16 h0 = __float2bfloat16_rn(p0), h1 = __float2bfloat16_rn(p1);
            bf16 h2 = __float2bfloat16_rn(p2), h3 = __float2bfloat16_rn(p3);
            phiA[nf] = packb(h0, h1);
            phiB[nf] = packb(h2, h3);
            ploA[nf] = packb(__float2bfloat16_rn(p0 - __bfloat162float(h0)),
                             __float2bfloat16_rn(p1 - __bfloat162float(h1)));
            ploB[nf] = packb(__float2bfloat16_rn(p2 - __bfloat162float(h2)),
                             __float2bfloat16_rn(p3 - __bfloat162float(h3)));
        }
        psA += __shfl_xor_sync(0xffffffffu, psA, 1);
        psA += __shfl_xor_sync(0xffffffffu, psA, 2);
        psB += __shfl_xor_sync(0xffffffffu, psB, 1);
        psB += __shfl_xor_sync(0xffffffffu, psB, 2);

        lA = lA * alA + psA; lB = lB * alB + psB;
        mA = mnA; mB = mnB;
#pragma unroll
        for (int nt = 0; nt < 8; nt++) {
            oacc[nt][0] *= alA; oacc[nt][1] *= alA;
            oacc[nt][2] *= alB; oacc[nt][3] *= alB;
        }

#pragma unroll
        for (int kc = 0; kc < 4; kc++) {
            uint32_t ah[4] = { phiA[2 * kc], phiB[2 * kc],
                               phiA[2 * kc + 1], phiB[2 * kc + 1] };
            uint32_t al[4] = { ploA[2 * kc], ploB[2 * kc],
                               ploA[2 * kc + 1], ploB[2 * kc + 1] };
#pragma unroll
            for (int ntp = 0; ntp < 4; ntp++) {
                uint32_t vh[4], vl[4];
                const uint32_t ev =
                    (uint32_t)((kc * 16 + (lane & 15)) * 72
                               + ntp * 16 + ((lane >> 4) & 1) * 8) * 2;
                ldm_x4t(vh, smb + (kst + OVHI) * 2 + ev);
                ldm_x4t(vl, smb + (kst + OVLO) * 2 + ev);
#pragma unroll
                for (int hf = 0; hf < 2; hf++) {
                    float* oa = oacc[ntp * 2 + hf];
                    mma_bf16(oa, ah, &vh[hf * 2]);
                    mma_bf16(oa, al, &vh[hf * 2]);
                    mma_bf16(oa, ah, &vl[hf * 2]);
                }
            }
        }
        __syncthreads();
    }

    const float ivA = 1.f / lA, ivB = 1.f / lB;
    const size_t gra = (size_t)b * SEQ + rA;
#pragma unroll
    for (int nt = 0; nt < 8; nt++) {
        const int col = h * 64 + nt * 8 + tig * 2;
        const float v0 = oacc[nt][0] * ivA, v1 = oacc[nt][1] * ivA;
        const float v2 = oacc[nt][2] * ivB, v3 = oacc[nt][3] * ivB;
        bf16 h0 = __float2bfloat16_rn(v0), h1 = __float2bfloat16_rn(v1);
        bf16 h2 = __float2bfloat16_rn(v2), h3 = __float2bfloat16_rn(v3);
        const size_t iA = (gra * DMODEL + col) >> 1;
        const size_t iB = ((gra + 8) * DMODEL + col) >> 1;
        ((uint32_t*)ohi)[iA] = packb(h0, h1);
        ((uint32_t*)olo)[iA] = packb(__float2bfloat16_rn(v0 - __bfloat162float(h0)),
                                     __float2bfloat16_rn(v1 - __bfloat162float(h1)));
        ((uint32_t*)ohi)[iB] = packb(h2, h3);
        ((uint32_t*)olo)[iB] = packb(__float2bfloat16_rn(v2 - __bfloat162float(h2)),
                                     __float2bfloat16_rn(v3 - __bfloat162float(h3)));
    }
}

// ===========================================================================
extern "C" void kernel_launch(void* const* d_in, const int* in_sizes, int n_in,
                              void* d_out, int out_size)
{
    const float* q     = (const float*)d_in[0];
    const float* k     = (const float*)d_in[1];
    const float* v     = (const float*)d_in[2];
    const float* w_qkv = (const float*)d_in[3];
    const float* b_qkv = (const float*)d_in[4];
    const float* w_out = (const float*)d_in[5];
    const float* b_out = (const float*)d_in[6];
    float* out = (float*)d_out;

    bf16 *in_hi, *in_lo, *wqkv_hi, *wqkv_lo, *qkv_hi, *qkv_lo;
    bf16 *attn_hi, *attn_lo, *wout_hi, *wout_lo;
    cudaGetSymbolAddress((void**)&in_hi,   g_in_hi);
    cudaGetSymbolAddress((void**)&in_lo,   g_in_lo);
    cudaGetSymbolAddress((void**)&wqkv_hi, g_wqkv_hi);
    cudaGetSymbolAddress((void**)&wqkv_lo, g_wqkv_lo);
    cudaGetSymbolAddress((void**)&qkv_hi,  g_qkv_hi);
    cudaGetSymbolAddress((void**)&qkv_lo,  g_qkv_lo);
    cudaGetSymbolAddress((void**)&attn_hi, g_attn_hi);
    cudaGetSymbolAddress((void**)&attn_lo, g_attn_lo);
    cudaGetSymbolAddress((void**)&wout_hi, g_wout_hi);
    cudaGetSymbolAddress((void**)&wout_lo, g_wout_lo);

    cudaFuncSetAttribute(gemm_bf16<0>,
                         cudaFuncAttributeMaxDynamicSharedMemorySize, GEMM_SMEM);
    cudaFuncSetAttribute(gemm_bf16<1>,
                         cudaFuncAttributeMaxDynamicSharedMemorySize, GEMM_SMEM);
    cudaFuncSetAttribute(attn_mma,
                         cudaFuncAttributeMaxDynamicSharedMemorySize, ATTN_SMEM);

    // 0) splits
    split_concat<<<(MTOT * K3 / 4) / 256, 256>>>(q, k, v, in_hi, in_lo);
    split_plain<<<(K3 * K3 / 4) / 256, 256>>>(w_qkv, wqkv_hi, wqkv_lo);
    split_plain<<<(DMODEL * DMODEL / 4) / 256, 256>>>(w_out, wout_hi, wout_lo);

    // 1) QKV projection -> bf16 hi/lo qkv
    {
        dim3 g(K3 / BNN, MTOT / BMM);      // (24, 32)
        gemm_bf16<1><<<g, 512, GEMM_SMEM>>>(in_hi, in_lo, wqkv_hi, wqkv_lo,
                                            b_qkv, nullptr, qkv_hi, qkv_lo,
                                            MTOT, K3, K3);
    }

    // 2) attention -> bf16 hi/lo attn
    {
        dim3 g(SEQ / 128, NHEADS, BATCH);
        attn_mma<<<g, 256, ATTN_SMEM>>>(qkv_hi, qkv_lo, attn_hi, attn_lo);
    }

    // 3) output projection -> fp32 out
    {
        dim3 g(DMODEL / BNN, MTOT / BMM);  // (8, 32)
        gemm_bf16<0><<<g, 512, GEMM_SMEM>>>(attn_hi, attn_lo, wout_hi, wout_lo,
                                            b_out, out, nullptr, nullptr,
                                            MTOT, DMODEL, DMODEL);
    }
}

// round 8
// speedup vs baseline: 1.0169x; 1.0169x over previous
#include <cuda_runtime.h>
#include <cuda_bf16.h>
#include <math_constants.h>
#include <cstdint>

#define BATCH 4
#define SEQ   2048
#define DMODEL 1024
#define NHEADS 16
#define DHEAD 64
#define NEG_VAL (-32767.0f)
#define MTOT  (BATCH * SEQ)      // 8192
#define K3    (3 * DMODEL)       // 3072

typedef __nv_bfloat16 bf16;

// ---- global scratch (bf16 hi/lo split operands) ----
__device__ bf16 g_in_hi[(size_t)MTOT * K3];
__device__ bf16 g_in_lo[(size_t)MTOT * K3];
__device__ bf16 g_wqkv_hi[(size_t)K3 * K3];
__device__ bf16 g_wqkv_lo[(size_t)K3 * K3];
__device__ bf16 g_qkv_hi[(size_t)MTOT * K3];
__device__ bf16 g_qkv_lo[(size_t)MTOT * K3];
__device__ bf16 g_attn_hi[(size_t)MTOT * DMODEL];
__device__ bf16 g_attn_lo[(size_t)MTOT * DMODEL];
__device__ bf16 g_wout_hi[(size_t)DMODEL * DMODEL];
__device__ bf16 g_wout_lo[(size_t)DMODEL * DMODEL];

// ===========================================================================
// helpers
// ===========================================================================
__device__ __forceinline__ uint32_t smem_u32(const void* p) {
    uint32_t a;
    asm("{ .reg .u64 t; cvta.to.shared.u64 t, %1; cvt.u32.u64 %0, t; }"
        : "=r"(a) : "l"(p));
    return a;
}
__device__ __forceinline__ void ldm_x4(uint32_t* r, uint32_t addr) {
    asm volatile("ldmatrix.sync.aligned.m8n8.x4.shared.b16 {%0,%1,%2,%3}, [%4];"
                 : "=r"(r[0]), "=r"(r[1]), "=r"(r[2]), "=r"(r[3]) : "r"(addr));
}
__device__ __forceinline__ void ldm_x4t(uint32_t* r, uint32_t addr) {
    asm volatile("ldmatrix.sync.aligned.m8n8.x4.trans.shared.b16 {%0,%1,%2,%3}, [%4];"
                 : "=r"(r[0]), "=r"(r[1]), "=r"(r[2]), "=r"(r[3]) : "r"(addr));
}
__device__ __forceinline__ void mma_bf16(float* c, const uint32_t* a, const uint32_t* b) {
    asm volatile(
        "mma.sync.aligned.m16n8k16.row.col.f32.bf16.bf16.f32 "
        "{%0,%1,%2,%3}, {%4,%5,%6,%7}, {%8,%9}, {%0,%1,%2,%3};"
        : "+f"(c[0]), "+f"(c[1]), "+f"(c[2]), "+f"(c[3])
        : "r"(a[0]), "r"(a[1]), "r"(a[2]), "r"(a[3]), "r"(b[0]), "r"(b[1]));
}
__device__ __forceinline__ uint32_t packb(bf16 a, bf16 b) {
    uint16_t ua = *(uint16_t*)&a, ub = *(uint16_t*)&b;
    return (uint32_t)ua | ((uint32_t)ub << 16);
}
__device__ __forceinline__ void split4(float4 v, uint2& hi, uint2& lo) {
    bf16 hx = __float2bfloat16_rn(v.x);
    bf16 hy = __float2bfloat16_rn(v.y);
    bf16 hz = __float2bfloat16_rn(v.z);
    bf16 hw = __float2bfloat16_rn(v.w);
    bf16 lx = __float2bfloat16_rn(v.x - __bfloat162float(hx));
    bf16 ly = __float2bfloat16_rn(v.y - __bfloat162float(hy));
    bf16 lz = __float2bfloat16_rn(v.z - __bfloat162float(hz));
    bf16 lw = __float2bfloat16_rn(v.w - __bfloat162float(hw));
    hi.x = packb(hx, hy); hi.y = packb(hz, hw);
    lo.x = packb(lx, ly); lo.y = packb(lz, lw);
}
__device__ __forceinline__ void cp16(uint32_t s, const void* g) {
    asm volatile("cp.async.cg.shared.global [%0], [%1], 16;" :: "r"(s), "l"(g));
}

// ===========================================================================
// split kernels
// ===========================================================================
__global__ void __launch_bounds__(256) split_concat(
    const float* __restrict__ q, const float* __restrict__ k,
    const float* __restrict__ v, bf16* __restrict__ hi, bf16* __restrict__ lo)
{
    const int idx = blockIdx.x * 256 + threadIdx.x;        // float4 index
    const int row = idx / 768;
    const int rem = idx - row * 768;                        // 0..767
    const int seg = rem >> 8;
    const int cin = rem & 255;
    const float* src = (seg == 0) ? q : ((seg == 1) ? k : v);
    float4 val = *(const float4*)(src + (size_t)row * DMODEL + cin * 4);
    uint2 h, l;
    split4(val, h, l);
    const size_t de = (size_t)row * K3 + rem * 4;
    *(uint2*)(hi + de) = h;
    *(uint2*)(lo + de) = l;
}

__global__ void __launch_bounds__(256) split_plain(
    const float* __restrict__ src, bf16* __restrict__ hi, bf16* __restrict__ lo)
{
    const size_t idx = (size_t)(blockIdx.x * 256 + threadIdx.x) * 4;
    float4 val = *(const float4*)(src + idx);
    uint2 h, l;
    split4(val, h, l);
    *(uint2*)(hi + idx) = h;
    *(uint2*)(lo + idx) = l;
}

// ===========================================================================
// Pure-bf16 mma GEMM. CTA 128x128, BK=32, 128 threads (4 warps, 2x2 grid,
// warp tile 64x64), 2 CTAs/SM, 2-stage cp.async double buffer.
// C = (Ahi+Alo) @ (Bhi+Blo)^T + bias, 3-product compensation.
// ===========================================================================
// stage layout in bf16 elements (row stride 40)
#define S_AHI 0
#define S_ALO 5120
#define S_BHI 10240
#define S_BLO 15360
#define S_ELEMS 20480
#define S_BYTES (S_ELEMS * 2)        // 40960
#define GEMM_SMEM (2 * S_BYTES)      // 81920

template <int OMODE>
__global__ void __launch_bounds__(128, 2) gemm_bf16(
    const bf16* __restrict__ Ahi, const bf16* __restrict__ Alo,
    const bf16* __restrict__ Bhi, const bf16* __restrict__ Blo,
    const float* __restrict__ bias,
    float* __restrict__ C, bf16* __restrict__ Chi, bf16* __restrict__ Clo,
    int M, int N, int K)
{
    extern __shared__ __align__(128) char smraw[];
    const uint32_t smb = smem_u32(smraw);
    const int tid = threadIdx.x, lane = tid & 31, wid = tid >> 5;
    const int wm = wid & 1, wn = wid >> 1;      // 2x2 warp grid, warp tile 64x64
    const int m0 = blockIdx.y * 128, n0 = blockIdx.x * 128;

    float acc[4][8][4];
#pragma unroll
    for (int i = 0; i < 4; i++)
#pragma unroll
        for (int j = 0; j < 8; j++)
#pragma unroll
            for (int e = 0; e < 4; e++) acc[i][j][e] = 0.f;

    const int nkt = K >> 5;
    const int lr = tid >> 2;          // 0..31 base row
    const int c8 = (tid & 3) << 3;    // elem col 0,8,16,24

#define ISSUE_STAGE(sb_, k0_) do {                                            \
    const uint32_t _sb = (sb_);                                               \
    const int _k0 = (k0_);                                                    \
    _Pragma("unroll")                                                         \
    for (int i = 0; i < 4; i++) {                                             \
        const int row = lr + 32 * i;                                          \
        const uint32_t d = (uint32_t)(row * 40 + c8) * 2;                     \
        const size_t ga = (size_t)(m0 + row) * K + _k0 + c8;                  \
        const size_t gb = (size_t)(n0 + row) * K + _k0 + c8;                  \
        cp16(_sb + S_AHI * 2 + d, Ahi + ga);                                  \
        cp16(_sb + S_ALO * 2 + d, Alo + ga);                                  \
        cp16(_sb + S_BHI * 2 + d, Bhi + gb);                                  \
        cp16(_sb + S_BLO * 2 + d, Blo + gb);                                  \
    }                                                                         \
} while (0)

    // prologue: stage 0
    ISSUE_STAGE(smb, 0);
    asm volatile("cp.async.commit_group;");

    for (int kt = 0; kt < nkt; kt++) {
        if (kt + 1 < nkt) {
            ISSUE_STAGE(smb + ((kt + 1) & 1) * S_BYTES, (kt + 1) << 5);
            asm volatile("cp.async.commit_group;");
            asm volatile("cp.async.wait_group 1;");
        } else {
            asm volatile("cp.async.wait_group 0;");
        }
        __syncthreads();

        const uint32_t sb = smb + (kt & 1) * S_BYTES;
#pragma unroll
        for (int ks = 0; ks < 2; ks++) {
            // B fragments: 8 n-frags via 4 x4 loads per (hi,lo)
            uint32_t bh[4][4], bl[4][4];
#pragma unroll
            for (int pn = 0; pn < 4; pn++) {
                const uint32_t row = (uint32_t)(wn * 64 + pn * 16 + (lane & 7)
                                                + ((lane >> 4) & 1) * 8);
                const uint32_t kc = (uint32_t)(ks * 16 + ((lane >> 3) & 1) * 8);
                const uint32_t eo = (row * 40 + kc) * 2;
                ldm_x4(bh[pn], sb + S_BHI * 2 + eo);
                ldm_x4(bl[pn], sb + S_BLO * 2 + eo);
            }
#pragma unroll
            for (int mt = 0; mt < 4; mt++) {
                uint32_t ah[4], al[4];
                const uint32_t eo =
                    (uint32_t)((wm * 64 + mt * 16 + (lane & 15)) * 40
                               + ks * 16 + ((lane >> 4) & 1) * 8) * 2;
                ldm_x4(ah, sb + S_AHI * 2 + eo);
                ldm_x4(al, sb + S_ALO * 2 + eo);
#pragma unroll
                for (int pn = 0; pn < 4; pn++)
#pragma unroll
                    for (int hf = 0; hf < 2; hf++) {
                        float* a = acc[mt][pn * 2 + hf];
                        mma_bf16(a, ah, &bh[pn][hf * 2]);
                        mma_bf16(a, al, &bh[pn][hf * 2]);
                        mma_bf16(a, ah, &bl[pn][hf * 2]);
                    }
            }
        }
        __syncthreads();
    }
#undef ISSUE_STAGE

    // epilogue
#pragma unroll
    for (int mt = 0; mt < 4; mt++) {
        const int rg = m0 + wm * 64 + mt * 16 + (lane >> 2);
#pragma unroll
        for (int nf = 0; nf < 8; nf++) {
            const int c = n0 + wn * 64 + nf * 8 + (lane & 3) * 2;
            const float b0 = bias[c], b1 = bias[c + 1];
            const float v00 = acc[mt][nf][0] + b0, v01 = acc[mt][nf][1] + b1;
            const float v10 = acc[mt][nf][2] + b0, v11 = acc[mt][nf][3] + b1;
            if (OMODE == 0) {
                *(float2*)(C + (size_t)rg * N + c)       = make_float2(v00, v01);
                *(float2*)(C + (size_t)(rg + 8) * N + c) = make_float2(v10, v11);
            } else {
                bf16 h00 = __float2bfloat16_rn(v00), h01 = __float2bfloat16_rn(v01);
                bf16 h10 = __float2bfloat16_rn(v10), h11 = __float2bfloat16_rn(v11);
                bf16 l00 = __float2bfloat16_rn(v00 - __bfloat162float(h00));
                bf16 l01 = __float2bfloat16_rn(v01 - __bfloat162float(h01));
                bf16 l10 = __float2bfloat16_rn(v10 - __bfloat162float(h10));
                bf16 l11 = __float2bfloat16_rn(v11 - __bfloat162float(h11));
                ((uint32_t*)Chi)[((size_t)rg * N + c) >> 1]       = packb(h00, h01);
                ((uint32_t*)Clo)[((size_t)rg * N + c) >> 1]       = packb(l00, l01);
                ((uint32_t*)Chi)[((size_t)(rg + 8) * N + c) >> 1] = packb(h10, h11);
                ((uint32_t*)Clo)[((size_t)(rg + 8) * N + c) >> 1] = packb(l10, l11);
            }
        }
    }
}

// ===========================================================================
// Tensor-core causal flash attention (unchanged).
// ===========================================================================
#define SQHI 0
#define SQLO 9216
#define KV0   18432
#define KVSTG 18432
#define OKHI 0
#define OKLO 4608
#define OVHI 9216
#define OVLO 13824
#define ATTN_SMEM ((18432 + 2 * 18432) * 2)   // 110592 bytes

__global__ void __launch_bounds__(256, 2) attn_mma(
    const bf16* __restrict__ qkv_hi, const bf16* __restrict__ qkv_lo,
    bf16* __restrict__ ohi, bf16* __restrict__ olo)
{
    extern __shared__ __align__(128) char smraw[];
    const uint32_t smb = smem_u32(smraw);
    const int tid = threadIdx.x, lane = tid & 31, wid = tid >> 5;
    const int gid = lane >> 2, tig = lane & 3;
    const int bt = blockIdx.x, h = blockIdx.y, b = blockIdx.z;
    const int g0 = bt * 128;
    const int jtmax = 2 * bt + 1;

    {
#pragma unroll
        for (int t = 0; t < 4; t++) {
            const int idx = tid + t * 256;
            const int row = idx >> 3;
            const int c8 = (idx & 7) * 8;
            const size_t g = ((size_t)b * SEQ + g0 + row) * K3 + h * 64 + c8;
            const uint32_t so = (uint32_t)(row * 72 + c8);
            cp16(smb + (SQHI + so) * 2, qkv_hi + g);
            cp16(smb + (SQLO + so) * 2, qkv_lo + g);
        }
#pragma unroll
        for (int t = 0; t < 2; t++) {
            const int idx = tid + t * 256;
            const int row = idx >> 3;
            const int c8 = (idx & 7) * 8;
            const size_t g = ((size_t)b * SEQ + row) * K3 + h * 64 + c8;
            const uint32_t so = KV0 + (uint32_t)(row * 72 + c8);
            cp16(smb + (so + OKHI) * 2, qkv_hi + g + DMODEL);
            cp16(smb + (so + OKLO) * 2, qkv_lo + g + DMODEL);
            cp16(smb + (so + OVHI) * 2, qkv_hi + g + 2 * DMODEL);
            cp16(smb + (so + OVLO) * 2, qkv_lo + g + 2 * DMODEL);
        }
        asm volatile("cp.async.commit_group;");
    }

    float oacc[8][4];
#pragma unroll
    for (int i = 0; i < 8; i++)
#pragma unroll
        for (int e = 0; e < 4; e++) oacc[i][e] = 0.f;
    float mA = -CUDART_INF_F, mB = -CUDART_INF_F, lA = 0.f, lB = 0.f;

    const int wrow = g0 + wid * 16;
    const int rA = wrow + gid;

    for (int jt = 0; jt <= jtmax; jt++) {
        if (jt + 1 <= jtmax) {
            const int j1 = (jt + 1) * 64;
            const uint32_t stg = KV0 + ((jt + 1) & 1) * KVSTG;
#pragma unroll
            for (int t = 0; t < 2; t++) {
                const int idx = tid + t * 256;
                const int row = idx >> 3;
                const int c8 = (idx & 7) * 8;
                const size_t g = ((size_t)b * SEQ + j1 + row) * K3 + h * 64 + c8;
                const uint32_t so = stg + (uint32_t)(row * 72 + c8);
                cp16(smb + (so + OKHI) * 2, qkv_hi + g + DMODEL);
                cp16(smb + (so + OKLO) * 2, qkv_lo + g + DMODEL);
                cp16(smb + (so + OVHI) * 2, qkv_hi + g + 2 * DMODEL);
                cp16(smb + (so + OVLO) * 2, qkv_lo + g + 2 * DMODEL);
            }
            asm volatile("cp.async.commit_group;");
            asm volatile("cp.async.wait_group 1;");
        } else {
            asm volatile("cp.async.wait_group 0;");
        }
        __syncthreads();

        const uint32_t kst = KV0 + (jt & 1) * KVSTG;
        const int j0 = jt * 64;

        float sacc[8][4];
#pragma unroll
        for (int i = 0; i < 8; i++)
#pragma unroll
            for (int e = 0; e < 4; e++) sacc[i][e] = 0.f;

#pragma unroll
        for (int ks = 0; ks < 4; ks++) {
            uint32_t ah[4], al[4];
            const uint32_t eo =
                (uint32_t)((wid * 16 + (lane & 15)) * 72
                           + ks * 16 + ((lane >> 4) & 1) * 8) * 2;
            ldm_x4(ah, smb + SQHI * 2 + eo);
            ldm_x4(al, smb + SQLO * 2 + eo);
#pragma unroll
            for (int pf = 0; pf < 4; pf++) {
                uint32_t bh[4], bl[4];
                const uint32_t row = (uint32_t)(pf * 16 + (lane & 7)
                                                + ((lane >> 4) & 1) * 8);
                const uint32_t kc = (uint32_t)(ks * 16 + ((lane >> 3) & 1) * 8);
                const uint32_t eb = (row * 72 + kc) * 2;
                ldm_x4(bh, smb + (kst + OKHI) * 2 + eb);
                ldm_x4(bl, smb + (kst + OKLO) * 2 + eb);
#pragma unroll
                for (int hf = 0; hf < 2; hf++) {
                    float* sa = sacc[pf * 2 + hf];
                    mma_bf16(sa, ah, &bh[hf * 2]);
                    mma_bf16(sa, al, &bh[hf * 2]);
                    mma_bf16(sa, ah, &bl[hf * 2]);
                }
            }
        }

        const bool needmask = (j0 + 63 > wrow);
#pragma unroll
        for (int nf = 0; nf < 8; nf++) {
#pragma unroll
            for (int e = 0; e < 4; e++) {
                float vsc = sacc[nf][e] * 8.0f;
                if (needmask) {
                    const int col = j0 + nf * 8 + tig * 2 + (e & 1);
                    const int row = (e < 2) ? rA : (rA + 8);
                    if (col > row) vsc = NEG_VAL;
                }
                sacc[nf][e] = vsc;
            }
        }

        float mxA = -CUDART_INF_F, mxB = -CUDART_INF_F;
#pragma unroll
        for (int nf = 0; nf < 8; nf++) {
            mxA = fmaxf(mxA, fmaxf(sacc[nf][0], sacc[nf][1]));
            mxB = fmaxf(mxB, fmaxf(sacc[nf][2], sacc[nf][3]));
        }
        mxA = fmaxf(mxA, __shfl_xor_sync(0xffffffffu, mxA, 1));
        mxA = fmaxf(mxA, __shfl_xor_sync(0xffffffffu, mxA, 2));
        mxB = fmaxf(mxB, __shfl_xor_sync(0xffffffffu, mxB, 1));
        mxB = fmaxf(mxB, __shfl_xor_sync(0xffffffffu, mxB, 2));

        const float mnA = fmaxf(mA, mxA), mnB = fmaxf(mB, mxB);
        const float alA = __expf(mA - mnA), alB = __expf(mB - mnB);

        float psA = 0.f, psB = 0.f;
        uint32_t phiA[8], phiB[8], ploA[8], ploB[8];
#pragma unroll
        for (int nf = 0; nf < 8; nf++) {
            const float p0 = __expf(sacc[nf][0] - mnA);
            const float p1 = __expf(sacc[nf][1] - mnA);
            const float p2 = __expf(sacc[nf][2] - mnB);
            const float p3 = __expf(sacc[nf][3] - mnB);
            psA += p0 + p1; psB += p2 + p3;
            bf16 h0 = __float2bfloat16_rn(p0), h1 = __float2bfloat16_rn(p1);
            bf16 h2 = __float2bfloat16_rn(p2), h3 = __float2bfloat16_rn(p3);
            phiA[nf] = packb(h0, h1);
            phiB[nf] = packb(h2, h3);
            ploA[nf] = packb(__float2bfloat16_rn(p0 - __bfloat162float(h0)),
                             __float2bfloat16_rn(p1 - __bfloat162float(h1)));
            ploB[nf] = packb(__float2bfloat16_rn(p2 - __bfloat162float(h2)),
                             __float2bfloat16_rn(p3 - __bfloat162float(h3)));
        }
        psA += __shfl_xor_sync(0xffffffffu, psA, 1);
        psA += __shfl_xor_sync(0xffffffffu, psA, 2);
        psB += __shfl_xor_sync(0xffffffffu, psB, 1);
        psB += __shfl_xor_sync(0xffffffffu, psB, 2);

        lA = lA * alA + psA; lB = lB * alB + psB;
        mA = mnA; mB = mnB;
#pragma unroll
        for (int nt = 0; nt < 8; nt++) {
            oacc[nt][0] *= alA; oacc[nt][1] *= alA;
            oacc[nt][2] *= alB; oacc[nt][3] *= alB;
        }

#pragma unroll
        for (int kc = 0; kc < 4; kc++) {
            uint32_t ah[4] = { phiA[2 * kc], phiB[2 * kc],
                               phiA[2 * kc + 1], phiB[2 * kc + 1] };
            uint32_t al[4] = { ploA[2 * kc], ploB[2 * kc],
                               ploA[2 * kc + 1], ploB[2 * kc + 1] };
#pragma unroll
            for (int ntp = 0; ntp < 4; ntp++) {
                uint32_t vh[4], vl[4];
                const uint32_t ev =
                    (uint32_t)((kc * 16 + (lane & 15)) * 72
                               + ntp * 16 + ((lane >> 4) & 1) * 8) * 2;
                ldm_x4t(vh, smb + (kst + OVHI) * 2 + ev);
                ldm_x4t(vl, smb + (kst + OVLO) * 2 + ev);
#pragma unroll
                for (int hf = 0; hf < 2; hf++) {
                    float* oa = oacc[ntp * 2 + hf];
                    mma_bf16(oa, ah, &vh[hf * 2]);
                    mma_bf16(oa, al, &vh[hf * 2]);
                    mma_bf16(oa, ah, &vl[hf * 2]);
                }
            }
        }
        __syncthreads();
    }

    const float ivA = 1.f / lA, ivB = 1.f / lB;
    const size_t gra = (size_t)b * SEQ + rA;
#pragma unroll
    for (int nt = 0; nt < 8; nt++) {
        const int col = h * 64 + nt * 8 + tig * 2;
        const float v0 = oacc[nt][0] * ivA, v1 = oacc[nt][1] * ivA;
        const float v2 = oacc[nt][2] * ivB, v3 = oacc[nt][3] * ivB;
        bf16 h0 = __float2bfloat16_rn(v0), h1 = __float2bfloat16_rn(v1);
        bf16 h2 = __float2bfloat16_rn(v2), h3 = __float2bfloat16_rn(v3);
        const size_t iA = (gra * DMODEL + col) >> 1;
        const size_t iB = ((gra + 8) * DMODEL + col) >> 1;
        ((uint32_t*)ohi)[iA] = packb(h0, h1);
        ((uint32_t*)olo)[iA] = packb(__float2bfloat16_rn(v0 - __bfloat162float(h0)),
                                     __float2bfloat16_rn(v1 - __bfloat162float(h1)));
        ((uint32_t*)ohi)[iB] = packb(h2, h3);
        ((uint32_t*)olo)[iB] = packb(__float2bfloat16_rn(v2 - __bfloat162float(h2)),
                                     __float2bfloat16_rn(v3 - __bfloat162float(h3)));
    }
}

// ===========================================================================
extern "C" void kernel_launch(void* const* d_in, const int* in_sizes, int n_in,
                              void* d_out, int out_size)
{
    const float* q     = (const float*)d_in[0];
    const float* k     = (const float*)d_in[1];
    const float* v     = (const float*)d_in[2];
    const float* w_qkv = (const float*)d_in[3];
    const float* b_qkv = (const float*)d_in[4];
    const float* w_out = (const float*)d_in[5];
    const float* b_out = (const float*)d_in[6];
    float* out = (float*)d_out;

    bf16 *in_hi, *in_lo, *wqkv_hi, *wqkv_lo, *qkv_hi, *qkv_lo;
    bf16 *attn_hi, *attn_lo, *wout_hi, *wout_lo;
    cudaGetSymbolAddress((void**)&in_hi,   g_in_hi);
    cudaGetSymbolAddress((void**)&in_lo,   g_in_lo);
    cudaGetSymbolAddress((void**)&wqkv_hi, g_wqkv_hi);
    cudaGetSymbolAddress((void**)&wqkv_lo, g_wqkv_lo);
    cudaGetSymbolAddress((void**)&qkv_hi,  g_qkv_hi);
    cudaGetSymbolAddress((void**)&qkv_lo,  g_qkv_lo);
    cudaGetSymbolAddress((void**)&attn_hi, g_attn_hi);
    cudaGetSymbolAddress((void**)&attn_lo, g_attn_lo);
    cudaGetSymbolAddress((void**)&wout_hi, g_wout_hi);
    cudaGetSymbolAddress((void**)&wout_lo, g_wout_lo);

    cudaFuncSetAttribute(gemm_bf16<0>,
                         cudaFuncAttributeMaxDynamicSharedMemorySize, GEMM_SMEM);
    cudaFuncSetAttribute(gemm_bf16<1>,
                         cudaFuncAttributeMaxDynamicSharedMemorySize, GEMM_SMEM);
    cudaFuncSetAttribute(attn_mma,
                         cudaFuncAttributeMaxDynamicSharedMemorySize, ATTN_SMEM);

    // 0) splits
    split_concat<<<(MTOT * K3 / 4) / 256, 256>>>(q, k, v, in_hi, in_lo);
    split_plain<<<(K3 * K3 / 4) / 256, 256>>>(w_qkv, wqkv_hi, wqkv_lo);
    split_plain<<<(DMODEL * DMODEL / 4) / 256, 256>>>(w_out, wout_hi, wout_lo);

    // 1) QKV projection -> bf16 hi/lo qkv
    {
        dim3 g(K3 / 128, MTOT / 128);      // (24, 64)
        gemm_bf16<1><<<g, 128, GEMM_SMEM>>>(in_hi, in_lo, wqkv_hi, wqkv_lo,
                                            b_qkv, nullptr, qkv_hi, qkv_lo,
                                            MTOT, K3, K3);
    }

    // 2) attention -> bf16 hi/lo attn
    {
        dim3 g(SEQ / 128, NHEADS, BATCH);
        attn_mma<<<g, 256, ATTN_SMEM>>>(qkv_hi, qkv_lo, attn_hi, attn_lo);
    }

    // 3) output projection -> fp32 out
    {
        dim3 g(DMODEL / 128, MTOT / 128);  // (8, 64)
        gemm_bf16<0><<<g, 128, GEMM_SMEM>>>(attn_hi, attn_lo, wout_hi, wout_lo,
                                            b_out, out, nullptr, nullptr,
                                            MTOT, DMODEL, DMODEL);
    }
}

// round 11
// speedup vs baseline: 1.1703x; 1.1508x over previous
#include <cuda_runtime.h>
#include <cuda_fp16.h>
#include <math_constants.h>
#include <cstdint>

#define BATCH 4
#define SEQ   2048
#define DMODEL 1024
#define NHEADS 16
#define DHEAD 64
#define NEG_VAL (-32767.0f)
#define MTOT  (BATCH * SEQ)      // 8192
#define K3    (3 * DMODEL)       // 3072

typedef __half fp16;

// ---- global scratch ----
__device__ fp16 g_in_h [(size_t)MTOT * K3];      // input hi
__device__ fp16 g_in_l [(size_t)MTOT * K3];      // input lo (exact pair)
__device__ fp16 g_wqkv_h[(size_t)K3 * K3];
__device__ fp16 g_wqkv_l[(size_t)K3 * K3];
__device__ fp16 g_qkv_h[(size_t)MTOT * K3];      // qkv hi
__device__ fp16 g_qkv_l[(size_t)MTOT * K3];      // qkv lo (q,k thirds only)
__device__ fp16 g_attn_h[(size_t)MTOT * DMODEL]; // attention out (single)
__device__ fp16 g_wout_h[(size_t)DMODEL * DMODEL];
__device__ fp16 g_wout_l[(size_t)DMODEL * DMODEL];

// ===========================================================================
// helpers
// ===========================================================================
__device__ __forceinline__ uint32_t smem_u32(const void* p) {
    uint32_t a;
    asm("{ .reg .u64 t; cvta.to.shared.u64 t, %1; cvt.u32.u64 %0, t; }"
        : "=r"(a) : "l"(p));
    return a;
}
__device__ __forceinline__ void ldm_x4(uint32_t* r, uint32_t addr) {
    asm volatile("ldmatrix.sync.aligned.m8n8.x4.shared.b16 {%0,%1,%2,%3}, [%4];"
                 : "=r"(r[0]), "=r"(r[1]), "=r"(r[2]), "=r"(r[3]) : "r"(addr));
}
__device__ __forceinline__ void ldm_x4t(uint32_t* r, uint32_t addr) {
    asm volatile("ldmatrix.sync.aligned.m8n8.x4.trans.shared.b16 {%0,%1,%2,%3}, [%4];"
                 : "=r"(r[0]), "=r"(r[1]), "=r"(r[2]), "=r"(r[3]) : "r"(addr));
}
__device__ __forceinline__ void mma_f16(float* c, const uint32_t* a, const uint32_t* b) {
    asm volatile(
        "mma.sync.aligned.m16n8k16.row.col.f32.f16.f16.f32 "
        "{%0,%1,%2,%3}, {%4,%5,%6,%7}, {%8,%9}, {%0,%1,%2,%3};"
        : "+f"(c[0]), "+f"(c[1]), "+f"(c[2]), "+f"(c[3])
        : "r"(a[0]), "r"(a[1]), "r"(a[2]), "r"(a[3]), "r"(b[0]), "r"(b[1]));
}
__device__ __forceinline__ uint32_t packh(fp16 a, fp16 b) {
    uint16_t ua = *(uint16_t*)&a, ub = *(uint16_t*)&b;
    return (uint32_t)ua | ((uint32_t)ub << 16);
}
__device__ __forceinline__ void split4h(float4 v, uint2& hi, uint2& lo) {
    fp16 hx = __float2half_rn(v.x), hy = __float2half_rn(v.y);
    fp16 hz = __float2half_rn(v.z), hw = __float2half_rn(v.w);
    fp16 lx = __float2half_rn(v.x - __half2float(hx));
    fp16 ly = __float2half_rn(v.y - __half2float(hy));
    fp16 lz = __float2half_rn(v.z - __half2float(hz));
    fp16 lw = __float2half_rn(v.w - __half2float(hw));
    hi.x = packh(hx, hy); hi.y = packh(hz, hw);
    lo.x = packh(lx, ly); lo.y = packh(lz, lw);
}
__device__ __forceinline__ void cp16(uint32_t s, const void* g) {
    asm volatile("cp.async.cg.shared.global [%0], [%1], 16;" :: "r"(s), "l"(g));
}

// ===========================================================================
// split kernels
// ===========================================================================
__global__ void __launch_bounds__(256) split_concat_hl(
    const float* __restrict__ q, const float* __restrict__ k,
    const float* __restrict__ v, fp16* __restrict__ hi, fp16* __restrict__ lo)
{
    const int idx = blockIdx.x * 256 + threadIdx.x;        // float4 index
    const int row = idx / 768;
    const int rem = idx - row * 768;
    const int seg = rem >> 8;
    const int cin = rem & 255;
    const float* src = (seg == 0) ? q : ((seg == 1) ? k : v);
    float4 val = *(const float4*)(src + (size_t)row * DMODEL + cin * 4);
    uint2 h, l;
    split4h(val, h, l);
    const size_t de = (size_t)row * K3 + rem * 4;
    *(uint2*)(hi + de) = h;
    *(uint2*)(lo + de) = l;
}

__global__ void __launch_bounds__(256) split_w_hl(
    const float* __restrict__ src, fp16* __restrict__ hi, fp16* __restrict__ lo)
{
    const size_t idx = (size_t)(blockIdx.x * 256 + threadIdx.x) * 4;
    float4 val = *(const float4*)(src + idx);
    uint2 h, l;
    split4h(val, h, l);
    *(uint2*)(hi + idx) = h;
    *(uint2*)(lo + idx) = l;
}

// ===========================================================================
// GEMM1: qkv = x @ Wqkv^T + b.  CTA 128x128, BK=32, 256 thr (2x4 warps,
// warp tile 64x32), 2-stage cp.async, 2 CTAs/SM.
// qk columns (n0<2048): 3 products AhWh+AlWh+AhWl (error ~2^-22), out hi+lo.
// v  columns (n0>=2048): 2 products (Ah+Al)Wh (exact A), out hi only.
// ===========================================================================
#define S1_AH 0
#define S1_AL 5120
#define S1_WH 10240
#define S1_WL 15360
#define S1_ELEMS 20480
#define S1_BYTES (S1_ELEMS * 2)       // 40960
#define GEMM1_SMEM (2 * S1_BYTES)     // 81920

__global__ void __launch_bounds__(256, 2) gemm1_f16(
    const fp16* __restrict__ Ah, const fp16* __restrict__ Al,
    const fp16* __restrict__ Wh, const fp16* __restrict__ Wl,
    const float* __restrict__ bias,
    fp16* __restrict__ Chi, fp16* __restrict__ Clo)
{
    const int M = MTOT, N = K3, K = K3;
    extern __shared__ __align__(128) char smraw[];
    const uint32_t smb = smem_u32(smraw);
    const int tid = threadIdx.x, lane = tid & 31, wid = tid >> 5;
    const int wm = wid & 1, wn = wid >> 1;
    const int m0 = blockIdx.y * 128, n0 = blockIdx.x * 128;
    const bool qk = (n0 < 2 * DMODEL);

    float acc[4][4][4];
#pragma unroll
    for (int i = 0; i < 4; i++)
#pragma unroll
        for (int j = 0; j < 4; j++)
#pragma unroll
            for (int e = 0; e < 4; e++) acc[i][j][e] = 0.f;

    const int nkt = K >> 5;

#define ISSUE1(sb_, k0_) do {                                                 \
    const uint32_t _sb = (sb_);                                               \
    const int _k0 = (k0_);                                                    \
    _Pragma("unroll")                                                         \
    for (int t = 0; t < 2; t++) {                                             \
        const int idx = tid + t * 256;                                        \
        const int row = idx >> 2;                                             \
        const int c8 = (idx & 3) << 3;                                        \
        const uint32_t d = (uint32_t)(row * 40 + c8) * 2;                     \
        const size_t ga = (size_t)(m0 + row) * K + _k0 + c8;                  \
        const size_t gw = (size_t)(n0 + row) * K + _k0 + c8;                  \
        cp16(_sb + S1_AH * 2 + d, Ah + ga);                                   \
        cp16(_sb + S1_AL * 2 + d, Al + ga);                                   \
        cp16(_sb + S1_WH * 2 + d, Wh + gw);                                   \
        if (qk) cp16(_sb + S1_WL * 2 + d, Wl + gw);                           \
    }                                                                         \
} while (0)

    ISSUE1(smb, 0);
    asm volatile("cp.async.commit_group;");

    for (int kt = 0; kt < nkt; kt++) {
        if (kt + 1 < nkt) {
            ISSUE1(smb + ((kt + 1) & 1) * S1_BYTES, (kt + 1) << 5);
            asm volatile("cp.async.commit_group;");
            asm volatile("cp.async.wait_group 1;");
        } else {
            asm volatile("cp.async.wait_group 0;");
        }
        __syncthreads();

        const uint32_t sb = smb + (kt & 1) * S1_BYTES;
#pragma unroll
        for (int ks = 0; ks < 2; ks++) {
            uint32_t wh[2][4], wl[2][4];
#pragma unroll
            for (int p = 0; p < 2; p++) {
                const uint32_t row = (uint32_t)(wn * 32 + p * 16 + (lane & 7)
                                                + ((lane >> 4) & 1) * 8);
                const uint32_t kc = (uint32_t)(ks * 16 + ((lane >> 3) & 1) * 8);
                const uint32_t eo = (row * 40 + kc) * 2;
                ldm_x4(wh[p], sb + S1_WH * 2 + eo);
                if (qk) ldm_x4(wl[p], sb + S1_WL * 2 + eo);
            }
#pragma unroll
            for (int mt = 0; mt < 4; mt++) {
                uint32_t ah[4], al[4];
                const uint32_t eo =
                    (uint32_t)((wm * 64 + mt * 16 + (lane & 15)) * 40
                               + ks * 16 + ((lane >> 4) & 1) * 8) * 2;
                ldm_x4(ah, sb + S1_AH * 2 + eo);
                ldm_x4(al, sb + S1_AL * 2 + eo);
#pragma unroll
                for (int p = 0; p < 2; p++)
#pragma unroll
                    for (int hf = 0; hf < 2; hf++) {
                        float* a = acc[mt][p * 2 + hf];
                        mma_f16(a, ah, &wh[p][hf * 2]);
                        mma_f16(a, al, &wh[p][hf * 2]);
                        if (qk) mma_f16(a, ah, &wl[p][hf * 2]);
                    }
            }
        }
        __syncthreads();
    }
#undef ISSUE1

    // epilogue: bias, hi always, lo for qk columns
#pragma unroll
    for (int mt = 0; mt < 4; mt++) {
        const int rg = m0 + wm * 64 + mt * 16 + (lane >> 2);
#pragma unroll
        for (int nf = 0; nf < 4; nf++) {
            const int c = n0 + wn * 32 + nf * 8 + (lane & 3) * 2;
            const float b0 = bias[c], b1 = bias[c + 1];
            const float v00 = acc[mt][nf][0] + b0, v01 = acc[mt][nf][1] + b1;
            const float v10 = acc[mt][nf][2] + b0, v11 = acc[mt][nf][3] + b1;
            fp16 h00 = __float2half_rn(v00), h01 = __float2half_rn(v01);
            fp16 h10 = __float2half_rn(v10), h11 = __float2half_rn(v11);
            ((uint32_t*)Chi)[((size_t)rg * N + c) >> 1]       = packh(h00, h01);
            ((uint32_t*)Chi)[((size_t)(rg + 8) * N + c) >> 1] = packh(h10, h11);
            if (qk) {
                fp16 l00 = __float2half_rn(v00 - __half2float(h00));
                fp16 l01 = __float2half_rn(v01 - __half2float(h01));
                fp16 l10 = __float2half_rn(v10 - __half2float(h10));
                fp16 l11 = __float2half_rn(v11 - __half2float(h11));
                ((uint32_t*)Clo)[((size_t)rg * N + c) >> 1]       = packh(l00, l01);
                ((uint32_t*)Clo)[((size_t)(rg + 8) * N + c) >> 1] = packh(l10, l11);
            }
        }
    }
}

// ===========================================================================
// GEMM2: out = attn @ (Wh+Wl)^T + b.  A single fp16 (exact W -> 2 products).
// fp32 output.
// ===========================================================================
#define S2_A  0
#define S2_WH 5120
#define S2_WL 10240
#define S2_ELEMS 15360
#define S2_BYTES (S2_ELEMS * 2)       // 30720
#define GEMM2_SMEM (2 * S2_BYTES)     // 61440

__global__ void __launch_bounds__(256, 2) gemm2_f16(
    const fp16* __restrict__ A, const fp16* __restrict__ Wh,
    const fp16* __restrict__ Wl, const float* __restrict__ bias,
    float* __restrict__ C)
{
    const int M = MTOT, N = DMODEL, K = DMODEL;
    extern __shared__ __align__(128) char smraw[];
    const uint32_t smb = smem_u32(smraw);
    const int tid = threadIdx.x, lane = tid & 31, wid = tid >> 5;
    const int wm = wid & 1, wn = wid >> 1;
    const int m0 = blockIdx.y * 128, n0 = blockIdx.x * 128;

    float acc[4][4][4];
#pragma unroll
    for (int i = 0; i < 4; i++)
#pragma unroll
        for (int j = 0; j < 4; j++)
#pragma unroll
            for (int e = 0; e < 4; e++) acc[i][j][e] = 0.f;

    const int nkt = K >> 5;

#define ISSUE2(sb_, k0_) do {                                                 \
    const uint32_t _sb = (sb_);                                               \
    const int _k0 = (k0_);                                                    \
    _Pragma("unroll")                                                         \
    for (int t = 0; t < 2; t++) {                                             \
        const int idx = tid + t * 256;                                        \
        const int row = idx >> 2;                                             \
        const int c8 = (idx & 3) << 3;                                        \
        const uint32_t d = (uint32_t)(row * 40 + c8) * 2;                     \
        const size_t ga = (size_t)(m0 + row) * K + _k0 + c8;                  \
        const size_t gw = (size_t)(n0 + row) * K + _k0 + c8;                  \
        cp16(_sb + S2_A  * 2 + d, A  + ga);                                   \
        cp16(_sb + S2_WH * 2 + d, Wh + gw);                                   \
        cp16(_sb + S2_WL * 2 + d, Wl + gw);                                   \
    }                                                                         \
} while (0)

    ISSUE2(smb, 0);
    asm volatile("cp.async.commit_group;");

    for (int kt = 0; kt < nkt; kt++) {
        if (kt + 1 < nkt) {
            ISSUE2(smb + ((kt + 1) & 1) * S2_BYTES, (kt + 1) << 5);
            asm volatile("cp.async.commit_group;");
            asm volatile("cp.async.wait_group 1;");
        } else {
            asm volatile("cp.async.wait_group 0;");
        }
        __syncthreads();

        const uint32_t sb = smb + (kt & 1) * S2_BYTES;
#pragma unroll
        for (int ks = 0; ks < 2; ks++) {
            uint32_t wh[2][4], wl[2][4];
#pragma unroll
            for (int p = 0; p < 2; p++) {
                const uint32_t row = (uint32_t)(wn * 32 + p * 16 + (lane & 7)
                                                + ((lane >> 4) & 1) * 8);
                const uint32_t kc = (uint32_t)(ks * 16 + ((lane >> 3) & 1) * 8);
                const uint32_t eo = (row * 40 + kc) * 2;
                ldm_x4(wh[p], sb + S2_WH * 2 + eo);
                ldm_x4(wl[p], sb + S2_WL * 2 + eo);
            }
#pragma unroll
            for (int mt = 0; mt < 4; mt++) {
                uint32_t af[4];
                const uint32_t eo =
                    (uint32_t)((wm * 64 + mt * 16 + (lane & 15)) * 40
                               + ks * 16 + ((lane >> 4) & 1) * 8) * 2;
                ldm_x4(af, sb + S2_A * 2 + eo);
#pragma unroll
                for (int p = 0; p < 2; p++)
#pragma unroll
                    for (int hf = 0; hf < 2; hf++) {
                        float* a = acc[mt][p * 2 + hf];
                        mma_f16(a, af, &wh[p][hf * 2]);
                        mma_f16(a, af, &wl[p][hf * 2]);
                    }
            }
        }
        __syncthreads();
    }
#undef ISSUE2

#pragma unroll
    for (int mt = 0; mt < 4; mt++) {
        const int rg = m0 + wm * 64 + mt * 16 + (lane >> 2);
#pragma unroll
        for (int nf = 0; nf < 4; nf++) {
            const int c = n0 + wn * 32 + nf * 8 + (lane & 3) * 2;
            const float b0 = bias[c], b1 = bias[c + 1];
            *(float2*)(C + (size_t)rg * N + c) =
                make_float2(acc[mt][nf][0] + b0, acc[mt][nf][1] + b1);
            *(float2*)(C + (size_t)(rg + 8) * N + c) =
                make_float2(acc[mt][nf][2] + b0, acc[mt][nf][3] + b1);
        }
    }
}

// ===========================================================================
// fp16 causal flash attention.
// Q exact (hi/lo), K exact (hi/lo): QK = 3 products (error ~2^-22).
// P exact (hi/lo in regs), V single: PV = 2 products.
// CTA = (128 q-rows, head, batch); 8 warps; KV tile 64 double-buffered.
// ===========================================================================
#define SQH 0
#define SQL 9216
#define AKV0 18432            // stage base (elements)
#define AKVSTG 13824          // per stage: KH 4608 + KL 4608 + VH 4608
#define A_KL 4608
#define A_VH 9216
#define ATTN_SMEM ((18432 + 2 * 13824) * 2)   // 92160 bytes

__global__ void __launch_bounds__(256, 2) attn_f16(
    const fp16* __restrict__ qkv_h, const fp16* __restrict__ qkv_l,
    fp16* __restrict__ oh)
{
    extern __shared__ __align__(128) char smraw[];
    const uint32_t smb = smem_u32(smraw);
    const int tid = threadIdx.x, lane = tid & 31, wid = tid >> 5;
    const int gid = lane >> 2, tig = lane & 3;
    const int bt = blockIdx.x, h = blockIdx.y, b = blockIdx.z;
    const int g0 = bt * 128;
    const int jtmax = 2 * bt + 1;

    // ---- prologue: Q (hi+lo) + KV stage 0 ----
    {
#pragma unroll
        for (int t = 0; t < 4; t++) {
            const int idx = tid + t * 256;
            const int row = idx >> 3;
            const int c8 = (idx & 7) * 8;
            const size_t g = ((size_t)b * SEQ + g0 + row) * K3 + h * 64 + c8;
            const uint32_t so = (uint32_t)(row * 72 + c8);
            cp16(smb + (SQH + so) * 2, qkv_h + g);
            cp16(smb + (SQL + so) * 2, qkv_l + g);
        }
#pragma unroll
        for (int t = 0; t < 2; t++) {
            const int idx = tid + t * 256;
            const int row = idx >> 3;
            const int c8 = (idx & 7) * 8;
            const size_t g = ((size_t)b * SEQ + row) * K3 + h * 64 + c8;
            const uint32_t so = AKV0 + (uint32_t)(row * 72 + c8);
            cp16(smb + so * 2, qkv_h + g + DMODEL);                  // K hi
            cp16(smb + (so + A_KL) * 2, qkv_l + g + DMODEL);         // K lo
            cp16(smb + (so + A_VH) * 2, qkv_h + g + 2 * DMODEL);     // V
        }
        asm volatile("cp.async.commit_group;");
    }

    float oacc[8][4];
#pragma unroll
    for (int i = 0; i < 8; i++)
#pragma unroll
        for (int e = 0; e < 4; e++) oacc[i][e] = 0.f;
    float mA = -CUDART_INF_F, mB = -CUDART_INF_F, lA = 0.f, lB = 0.f;

    const int wrow = g0 + wid * 16;
    const int rA = wrow + gid;

    for (int jt = 0; jt <= jtmax; jt++) {
        if (jt + 1 <= jtmax) {
            const int j1 = (jt + 1) * 64;
            const uint32_t stg = AKV0 + ((jt + 1) & 1) * AKVSTG;
#pragma unroll
            for (int t = 0; t < 2; t++) {
                const int idx = tid + t * 256;
                const int row = idx >> 3;
                const int c8 = (idx & 7) * 8;
                const size_t g = ((size_t)b * SEQ + j1 + row) * K3 + h * 64 + c8;
                const uint32_t so = stg + (uint32_t)(row * 72 + c8);
                cp16(smb + so * 2, qkv_h + g + DMODEL);
                cp16(smb + (so + A_KL) * 2, qkv_l + g + DMODEL);
                cp16(smb + (so + A_VH) * 2, qkv_h + g + 2 * DMODEL);
            }
            asm volatile("cp.async.commit_group;");
            asm volatile("cp.async.wait_group 1;");
        } else {
            asm volatile("cp.async.wait_group 0;");
        }
        __syncthreads();

        const uint32_t kst = AKV0 + (jt & 1) * AKVSTG;
        const int j0 = jt * 64;

        // ---- S = Q @ K^T (3 products) ----
        float sacc[8][4];
#pragma unroll
        for (int i = 0; i < 8; i++)
#pragma unroll
            for (int e = 0; e < 4; e++) sacc[i][e] = 0.f;

#pragma unroll
        for (int ks = 0; ks < 4; ks++) {
            uint32_t ah[4], al[4];
            const uint32_t eo =
                (uint32_t)((wid * 16 + (lane & 15)) * 72
                           + ks * 16 + ((lane >> 4) & 1) * 8) * 2;
            ldm_x4(ah, smb + SQH * 2 + eo);
            ldm_x4(al, smb + SQL * 2 + eo);
#pragma unroll
            for (int pf = 0; pf < 4; pf++) {
                uint32_t kh[4], kl[4];
                const uint32_t row = (uint32_t)(pf * 16 + (lane & 7)
                                                + ((lane >> 4) & 1) * 8);
                const uint32_t kc = (uint32_t)(ks * 16 + ((lane >> 3) & 1) * 8);
                const uint32_t eb = (row * 72 + kc) * 2;
                ldm_x4(kh, smb + kst * 2 + eb);
                ldm_x4(kl, smb + (kst + A_KL) * 2 + eb);
#pragma unroll
                for (int hf = 0; hf < 2; hf++) {
                    float* sa = sacc[pf * 2 + hf];
                    mma_f16(sa, ah, &kh[hf * 2]);
                    mma_f16(sa, al, &kh[hf * 2]);
                    mma_f16(sa, ah, &kl[hf * 2]);
                }
            }
        }

        // ---- scale + causal mask ----
        const bool needmask = (j0 + 63 > wrow);
#pragma unroll
        for (int nf = 0; nf < 8; nf++) {
#pragma unroll
            for (int e = 0; e < 4; e++) {
                float vsc = sacc[nf][e] * 8.0f;
                if (needmask) {
                    const int col = j0 + nf * 8 + tig * 2 + (e & 1);
                    const int row = (e < 2) ? rA : (rA + 8);
                    if (col > row) vsc = NEG_VAL;
                }
                sacc[nf][e] = vsc;
            }
        }

        // ---- online softmax ----
        float mxA = -CUDART_INF_F, mxB = -CUDART_INF_F;
#pragma unroll
        for (int nf = 0; nf < 8; nf++) {
            mxA = fmaxf(mxA, fmaxf(sacc[nf][0], sacc[nf][1]));
            mxB = fmaxf(mxB, fmaxf(sacc[nf][2], sacc[nf][3]));
        }
        mxA = fmaxf(mxA, __shfl_xor_sync(0xffffffffu, mxA, 1));
        mxA = fmaxf(mxA, __shfl_xor_sync(0xffffffffu, mxA, 2));
        mxB = fmaxf(mxB, __shfl_xor_sync(0xffffffffu, mxB, 1));
        mxB = fmaxf(mxB, __shfl_xor_sync(0xffffffffu, mxB, 2));

        const float mnA = fmaxf(mA, mxA), mnB = fmaxf(mB, mxB);
        const float alA = __expf(mA - mnA), alB = __expf(mB - mnB);

        float psA = 0.f, psB = 0.f;
        uint32_t phA[8], phB[8], plA[8], plB[8];
#pragma unroll
        for (int nf = 0; nf < 8; nf++) {
            const float p0 = __expf(sacc[nf][0] - mnA);
            const float p1 = __expf(sacc[nf][1] - mnA);
            const float p2 = __expf(sacc[nf][2] - mnB);
            const float p3 = __expf(sacc[nf][3] - mnB);
            psA += p0 + p1; psB += p2 + p3;
            fp16 h0 = __float2half_rn(p0), h1 = __float2half_rn(p1);
            fp16 h2 = __float2half_rn(p2), h3 = __float2half_rn(p3);
            phA[nf] = packh(h0, h1);
            phB[nf] = packh(h2, h3);
            plA[nf] = packh(__float2half_rn(p0 - __half2float(h0)),
                            __float2half_rn(p1 - __half2float(h1)));
            plB[nf] = packh(__float2half_rn(p2 - __half2float(h2)),
                            __float2half_rn(p3 - __half2float(h3)));
        }
        psA += __shfl_xor_sync(0xffffffffu, psA, 1);
        psA += __shfl_xor_sync(0xffffffffu, psA, 2);
        psB += __shfl_xor_sync(0xffffffffu, psB, 1);
        psB += __shfl_xor_sync(0xffffffffu, psB, 2);

        lA = lA * alA + psA; lB = lB * alB + psB;
        mA = mnA; mB = mnB;
#pragma unroll
        for (int nt = 0; nt < 8; nt++) {
            oacc[nt][0] *= alA; oacc[nt][1] *= alA;
            oacc[nt][2] *= alB; oacc[nt][3] *= alB;
        }

        // ---- O += P @ V (P exact, V single: 2 products) ----
#pragma unroll
        for (int kc = 0; kc < 4; kc++) {
            uint32_t ph[4] = { phA[2 * kc], phB[2 * kc],
                               phA[2 * kc + 1], phB[2 * kc + 1] };
            uint32_t pl[4] = { plA[2 * kc], plB[2 * kc],
                               plA[2 * kc + 1], plB[2 * kc + 1] };
#pragma unroll
            for (int ntp = 0; ntp < 4; ntp++) {
                uint32_t vh[4];
                const uint32_t ev =
                    (uint32_t)((kc * 16 + (lane & 15)) * 72
                               + ntp * 16 + ((lane >> 4) & 1) * 8) * 2;
                ldm_x4t(vh, smb + (kst + A_VH) * 2 + ev);
#pragma unroll
                for (int hf = 0; hf < 2; hf++) {
                    float* oa = oacc[ntp * 2 + hf];
                    mma_f16(oa, ph, &vh[hf * 2]);
                    mma_f16(oa, pl, &vh[hf * 2]);
                }
            }
        }
        __syncthreads();
    }

    // ---- epilogue: O/l -> single fp16 ----
    const float ivA = 1.f / lA, ivB = 1.f / lB;
    const size_t gra = (size_t)b * SEQ + rA;
#pragma unroll
    for (int nt = 0; nt < 8; nt++) {
        const int col = h * 64 + nt * 8 + tig * 2;
        const float v0 = oacc[nt][0] * ivA, v1 = oacc[nt][1] * ivA;
        const float v2 = oacc[nt][2] * ivB, v3 = oacc[nt][3] * ivB;
        ((uint32_t*)oh)[(gra * DMODEL + col) >> 1] =
            packh(__float2half_rn(v0), __float2half_rn(v1));
        ((uint32_t*)oh)[((gra + 8) * DMODEL + col) >> 1] =
            packh(__float2half_rn(v2), __float2half_rn(v3));
    }
}

// ===========================================================================
extern "C" void kernel_launch(void* const* d_in, const int* in_sizes, int n_in,
                              void* d_out, int out_size)
{
    const float* q     = (const float*)d_in[0];
    const float* k     = (const float*)d_in[1];
    const float* v     = (const float*)d_in[2];
    const float* w_qkv = (const float*)d_in[3];
    const float* b_qkv = (const float*)d_in[4];
    const float* w_out = (const float*)d_in[5];
    const float* b_out = (const float*)d_in[6];
    float* out = (float*)d_out;

    fp16 *in_h, *in_l, *wqkv_h, *wqkv_l, *qkv_h, *qkv_l, *attn_h, *wout_h, *wout_l;
    cudaGetSymbolAddress((void**)&in_h,   g_in_h);
    cudaGetSymbolAddress((void**)&in_l,   g_in_l);
    cudaGetSymbolAddress((void**)&wqkv_h, g_wqkv_h);
    cudaGetSymbolAddress((void**)&wqkv_l, g_wqkv_l);
    cudaGetSymbolAddress((void**)&qkv_h,  g_qkv_h);
    cudaGetSymbolAddress((void**)&qkv_l,  g_qkv_l);
    cudaGetSymbolAddress((void**)&attn_h, g_attn_h);
    cudaGetSymbolAddress((void**)&wout_h, g_wout_h);
    cudaGetSymbolAddress((void**)&wout_l, g_wout_l);

    cudaFuncSetAttribute(gemm1_f16,
                         cudaFuncAttributeMaxDynamicSharedMemorySize, GEMM1_SMEM);
    cudaFuncSetAttribute(gemm2_f16,
                         cudaFuncAttributeMaxDynamicSharedMemorySize, GEMM2_SMEM);
    cudaFuncSetAttribute(attn_f16,
                         cudaFuncAttributeMaxDynamicSharedMemorySize, ATTN_SMEM);

    // 0) splits
    split_concat_hl<<<(MTOT * K3 / 4) / 256, 256>>>(q, k, v, in_h, in_l);
    split_w_hl<<<(K3 * K3 / 4) / 256, 256>>>(w_qkv, wqkv_h, wqkv_l);
    split_w_hl<<<(DMODEL * DMODEL / 4) / 256, 256>>>(w_out, wout_h, wout_l);

    // 1) QKV projection
    {
        dim3 g(K3 / 128, MTOT / 128);      // (24, 64)
        gemm1_f16<<<g, 256, GEMM1_SMEM>>>(in_h, in_l, wqkv_h, wqkv_l,
                                          b_qkv, qkv_h, qkv_l);
    }

    // 2) attention
    {
        dim3 g(SEQ / 128, NHEADS, BATCH);
        attn_f16<<<g, 256, ATTN_SMEM>>>(qkv_h, qkv_l, attn_h);
    }

    // 3) output projection
    {
        dim3 g(DMODEL / 128, MTOT / 128);  // (8, 64)
        gemm2_f16<<<g, 256, GEMM2_SMEM>>>(attn_h, wout_h, wout_l, b_out, out);
    }
}

// round 16
// speedup vs baseline: 1.1932x; 1.0195x over previous
#include <cuda_runtime.h>
#include <cuda_fp16.h>
#include <math_constants.h>
#include <cstdint>

#define BATCH 4
#define SEQ   2048
#define DMODEL 1024
#define NHEADS 16
#define DHEAD 64
#define NEG_VAL (-32767.0f)
#define MTOT  (BATCH * SEQ)      // 8192
#define K3    (3 * DMODEL)       // 3072

typedef __half fp16;

// ---- global scratch ----
__device__ fp16 g_in_h [(size_t)MTOT * K3];      // input hi
__device__ fp16 g_in_l [(size_t)MTOT * K3];      // input lo (exact pair)
__device__ fp16 g_wqkv_h[(size_t)K3 * K3];
__device__ fp16 g_wqkv_l[(size_t)K3 * K3];
__device__ fp16 g_qkv_h[(size_t)MTOT * K3];      // qkv hi
__device__ fp16 g_qkv_l[(size_t)MTOT * K3];      // qkv lo (q,k thirds only)
__device__ fp16 g_attn_h[(size_t)MTOT * DMODEL]; // attention out (single)
__device__ fp16 g_wout_h[(size_t)DMODEL * DMODEL];
__device__ fp16 g_wout_l[(size_t)DMODEL * DMODEL];

// ===========================================================================
// helpers
// ===========================================================================
__device__ __forceinline__ uint32_t smem_u32(const void* p) {
    uint32_t a;
    asm("{ .reg .u64 t; cvta.to.shared.u64 t, %1; cvt.u32.u64 %0, t; }"
        : "=r"(a) : "l"(p));
    return a;
}
__device__ __forceinline__ void ldm_x4(uint32_t* r, uint32_t addr) {
    asm volatile("ldmatrix.sync.aligned.m8n8.x4.shared.b16 {%0,%1,%2,%3}, [%4];"
                 : "=r"(r[0]), "=r"(r[1]), "=r"(r[2]), "=r"(r[3]) : "r"(addr));
}
__device__ __forceinline__ void ldm_x4t(uint32_t* r, uint32_t addr) {
    asm volatile("ldmatrix.sync.aligned.m8n8.x4.trans.shared.b16 {%0,%1,%2,%3}, [%4];"
                 : "=r"(r[0]), "=r"(r[1]), "=r"(r[2]), "=r"(r[3]) : "r"(addr));
}
__device__ __forceinline__ void mma_f16(float* c, const uint32_t* a, const uint32_t* b) {
    asm volatile(
        "mma.sync.aligned.m16n8k16.row.col.f32.f16.f16.f32 "
        "{%0,%1,%2,%3}, {%4,%5,%6,%7}, {%8,%9}, {%0,%1,%2,%3};"
        : "+f"(c[0]), "+f"(c[1]), "+f"(c[2]), "+f"(c[3])
        : "r"(a[0]), "r"(a[1]), "r"(a[2]), "r"(a[3]), "r"(b[0]), "r"(b[1]));
}
__device__ __forceinline__ uint32_t packh(fp16 a, fp16 b) {
    uint16_t ua = *(uint16_t*)&a, ub = *(uint16_t*)&b;
    return (uint32_t)ua | ((uint32_t)ub << 16);
}
__device__ __forceinline__ void split4h(float4 v, uint2& hi, uint2& lo) {
    fp16 hx = __float2half_rn(v.x), hy = __float2half_rn(v.y);
    fp16 hz = __float2half_rn(v.z), hw = __float2half_rn(v.w);
    fp16 lx = __float2half_rn(v.x - __half2float(hx));
    fp16 ly = __float2half_rn(v.y - __half2float(hy));
    fp16 lz = __float2half_rn(v.z - __half2float(hz));
    fp16 lw = __float2half_rn(v.w - __half2float(hw));
    hi.x = packh(hx, hy); hi.y = packh(hz, hw);
    lo.x = packh(lx, ly); lo.y = packh(lz, lw);
}
__device__ __forceinline__ void cp16(uint32_t s, const void* g) {
    asm volatile("cp.async.cg.shared.global [%0], [%1], 16;" :: "r"(s), "l"(g));
}

// ===========================================================================
// split kernels
// ===========================================================================
__global__ void __launch_bounds__(256) split_concat_hl(
    const float* __restrict__ q, const float* __restrict__ k,
    const float* __restrict__ v, fp16* __restrict__ hi, fp16* __restrict__ lo)
{
    const int idx = blockIdx.x * 256 + threadIdx.x;        // float4 index
    const int row = idx / 768;
    const int rem = idx - row * 768;
    const int seg = rem >> 8;
    const int cin = rem & 255;
    const float* src = (seg == 0) ? q : ((seg == 1) ? k : v);
    float4 val = *(const float4*)(src + (size_t)row * DMODEL + cin * 4);
    uint2 h, l;
    split4h(val, h, l);
    const size_t de = (size_t)row * K3 + rem * 4;
    *(uint2*)(hi + de) = h;
    *(uint2*)(lo + de) = l;
}

__global__ void __launch_bounds__(256) split_w_hl(
    const float* __restrict__ src, fp16* __restrict__ hi, fp16* __restrict__ lo)
{
    const size_t idx = (size_t)(blockIdx.x * 256 + threadIdx.x) * 4;
    float4 val = *(const float4*)(src + idx);
    uint2 h, l;
    split4h(val, h, l);
    *(uint2*)(hi + idx) = h;
    *(uint2*)(lo + idx) = l;
}

// ===========================================================================
// GEMM1: qkv = x @ Wqkv^T + b.  CTA 128x128, BK=32, 256 thr (2x4 warps,
// warp tile 64x32), 2-stage cp.async, 2 CTAs/SM, single barrier per k-iter.
// qk columns (n0<2048): 3 products AhWh+AlWh+AhWl (error ~2^-22), out hi+lo.
// v  columns (n0>=2048): 1 product AhWh (value path, 2^-11 class), out hi.
// ===========================================================================
#define S1_AH 0
#define S1_AL 5120
#define S1_WH 10240
#define S1_WL 15360
#define S1_ELEMS 20480
#define S1_BYTES (S1_ELEMS * 2)       // 40960
#define GEMM1_SMEM (2 * S1_BYTES)     // 81920

__global__ void __launch_bounds__(256, 2) gemm1_f16(
    const fp16* __restrict__ Ah, const fp16* __restrict__ Al,
    const fp16* __restrict__ Wh, const fp16* __restrict__ Wl,
    const float* __restrict__ bias,
    fp16* __restrict__ Chi, fp16* __restrict__ Clo)
{
    const int N = K3, K = K3;
    extern __shared__ __align__(128) char smraw[];
    const uint32_t smb = smem_u32(smraw);
    const int tid = threadIdx.x, lane = tid & 31, wid = tid >> 5;
    const int wm = wid & 1, wn = wid >> 1;
    const int m0 = blockIdx.y * 128, n0 = blockIdx.x * 128;
    const bool qk = (n0 < 2 * DMODEL);

    float acc[4][4][4];
#pragma unroll
    for (int i = 0; i < 4; i++)
#pragma unroll
        for (int j = 0; j < 4; j++)
#pragma unroll
            for (int e = 0; e < 4; e++) acc[i][j][e] = 0.f;

    const int nkt = K >> 5;

#define ISSUE1(sb_, k0_) do {                                                 \
    const uint32_t _sb = (sb_);                                               \
    const int _k0 = (k0_);                                                    \
    _Pragma("unroll")                                                         \
    for (int t = 0; t < 2; t++) {                                             \
        const int idx = tid + t * 256;                                        \
        const int row = idx >> 2;                                             \
        const int c8 = (idx & 3) << 3;                                        \
        const uint32_t d = (uint32_t)(row * 40 + c8) * 2;                     \
        const size_t ga = (size_t)(m0 + row) * K + _k0 + c8;                  \
        const size_t gw = (size_t)(n0 + row) * K + _k0 + c8;                  \
        cp16(_sb + S1_AH * 2 + d, Ah + ga);                                   \
        cp16(_sb + S1_WH * 2 + d, Wh + gw);                                   \
        if (qk) {                                                             \
            cp16(_sb + S1_AL * 2 + d, Al + ga);                               \
            cp16(_sb + S1_WL * 2 + d, Wl + gw);                               \
        }                                                                     \
    }                                                                         \
} while (0)

    ISSUE1(smb, 0);
    asm volatile("cp.async.commit_group;");

    for (int kt = 0; kt < nkt; kt++) {
        asm volatile("cp.async.wait_group 0;");
        __syncthreads();
        if (kt + 1 < nkt) {
            ISSUE1(smb + ((kt + 1) & 1) * S1_BYTES, (kt + 1) << 5);
            asm volatile("cp.async.commit_group;");
        }

        const uint32_t sb = smb + (kt & 1) * S1_BYTES;
#pragma unroll
        for (int ks = 0; ks < 2; ks++) {
            uint32_t wh[2][4], wl[2][4];
#pragma unroll
            for (int p = 0; p < 2; p++) {
                const uint32_t row = (uint32_t)(wn * 32 + p * 16 + (lane & 7)
                                                + ((lane >> 4) & 1) * 8);
                const uint32_t kc = (uint32_t)(ks * 16 + ((lane >> 3) & 1) * 8);
                const uint32_t eo = (row * 40 + kc) * 2;
                ldm_x4(wh[p], sb + S1_WH * 2 + eo);
                if (qk) ldm_x4(wl[p], sb + S1_WL * 2 + eo);
            }
#pragma unroll
            for (int mt = 0; mt < 4; mt++) {
                uint32_t ah[4], al[4];
                const uint32_t eo =
                    (uint32_t)((wm * 64 + mt * 16 + (lane & 15)) * 40
                               + ks * 16 + ((lane >> 4) & 1) * 8) * 2;
                ldm_x4(ah, sb + S1_AH * 2 + eo);
                if (qk) ldm_x4(al, sb + S1_AL * 2 + eo);
#pragma unroll
                for (int p = 0; p < 2; p++)
#pragma unroll
                    for (int hf = 0; hf < 2; hf++) {
                        float* a = acc[mt][p * 2 + hf];
                        mma_f16(a, ah, &wh[p][hf * 2]);
                        if (qk) {
                            mma_f16(a, al, &wh[p][hf * 2]);
                            mma_f16(a, ah, &wl[p][hf * 2]);
                        }
                    }
            }
        }
        __syncthreads();   // all warps done reading buf[kt&1] before it is re-filled at kt+1
    }
#undef ISSUE1

    // epilogue: bias, hi always, lo for qk columns
#pragma unroll
    for (int mt = 0; mt < 4; mt++) {
        const int rg = m0 + wm * 64 + mt * 16 + (lane >> 2);
#pragma unroll
        for (int nf = 0; nf < 4; nf++) {
            const int c = n0 + wn * 32 + nf * 8 + (lane & 3) * 2;
            const float b0 = bias[c], b1 = bias[c + 1];
            const float v00 = acc[mt][nf][0] + b0, v01 = acc[mt][nf][1] + b1;
            const float v10 = acc[mt][nf][2] + b0, v11 = acc[mt][nf][3] + b1;
            fp16 h00 = __float2half_rn(v00), h01 = __float2half_rn(v01);
            fp16 h10 = __float2half_rn(v10), h11 = __float2half_rn(v11);
            ((uint32_t*)Chi)[((size_t)rg * N + c) >> 1]       = packh(h00, h01);
            ((uint32_t*)Chi)[((size_t)(rg + 8) * N + c) >> 1] = packh(h10, h11);
            if (qk) {
                fp16 l00 = __float2half_rn(v00 - __half2float(h00));
                fp16 l01 = __float2half_rn(v01 - __half2float(h01));
                fp16 l10 = __float2half_rn(v10 - __half2float(h10));
                fp16 l11 = __float2half_rn(v11 - __half2float(h11));
                ((uint32_t*)Clo)[((size_t)rg * N + c) >> 1]       = packh(l00, l01);
                ((uint32_t*)Clo)[((size_t)(rg + 8) * N + c) >> 1] = packh(l10, l11);
            }
        }
    }
}

// ===========================================================================
// GEMM2: out = attn @ (Wh+Wl)^T + b.  A single fp16, W exact: 2 products.
// fp32 output. Single barrier per k-iter.
// ===========================================================================
#define S2_A  0
#define S2_WH 5120
#define S2_WL 10240
#define S2_ELEMS 15360
#define S2_BYTES (S2_ELEMS * 2)       // 30720
#define GEMM2_SMEM (2 * S2_BYTES)     // 61440

__global__ void __launch_bounds__(256, 2) gemm2_f16(
    const fp16* __restrict__ A, const fp16* __restrict__ Wh,
    const fp16* __restrict__ Wl, const float* __restrict__ bias,
    float* __restrict__ C)
{
    const int N = DMODEL, K = DMODEL;
    extern __shared__ __align__(128) char smraw[];
    const uint32_t smb = smem_u32(smraw);
    const int tid = threadIdx.x, lane = tid & 31, wid = tid >> 5;
    const int wm = wid & 1, wn = wid >> 1;
    const int m0 = blockIdx.y * 128, n0 = blockIdx.x * 128;

    float acc[4][4][4];
#pragma unroll
    for (int i = 0; i < 4; i++)
#pragma unroll
        for (int j = 0; j < 4; j++)
#pragma unroll
            for (int e = 0; e < 4; e++) acc[i][j][e] = 0.f;

    const int nkt = K >> 5;

#define ISSUE2(sb_, k0_) do {                                                 \
    const uint32_t _sb = (sb_);                                               \
    const int _k0 = (k0_);                                                    \
    _Pragma("unroll")                                                         \
    for (int t = 0; t < 2; t++) {                                             \
        const int idx = tid + t * 256;                                        \
        const int row = idx >> 2;                                             \
        const int c8 = (idx & 3) << 3;                                        \
        const uint32_t d = (uint32_t)(row * 40 + c8) * 2;                     \
        const size_t ga = (size_t)(m0 + row) * K + _k0 + c8;                  \
        const size_t gw = (size_t)(n0 + row) * K + _k0 + c8;                  \
        cp16(_sb + S2_A  * 2 + d, A  + ga);                                   \
        cp16(_sb + S2_WH * 2 + d, Wh + gw);                                   \
        cp16(_sb + S2_WL * 2 + d, Wl + gw);                                   \
    }                                                                         \
} while (0)

    ISSUE2(smb, 0);
    asm volatile("cp.async.commit_group;");

    for (int kt = 0; kt < nkt; kt++) {
        asm volatile("cp.async.wait_group 0;");
        __syncthreads();
        if (kt + 1 < nkt) {
            ISSUE2(smb + ((kt + 1) & 1) * S2_BYTES, (kt + 1) << 5);
            asm volatile("cp.async.commit_group;");
        }

        const uint32_t sb = smb + (kt & 1) * S2_BYTES;
#pragma unroll
        for (int ks = 0; ks < 2; ks++) {
            uint32_t wh[2][4], wl[2][4];
#pragma unroll
            for (int p = 0; p < 2; p++) {
                const uint32_t row = (uint32_t)(wn * 32 + p * 16 + (lane & 7)
                                                + ((lane >> 4) & 1) * 8);
                const uint32_t kc = (uint32_t)(ks * 16 + ((lane >> 3) & 1) * 8);
                const uint32_t eo = (row * 40 + kc) * 2;
                ldm_x4(wh[p], sb + S2_WH * 2 + eo);
                ldm_x4(wl[p], sb + S2_WL * 2 + eo);
            }
#pragma unroll
            for (int mt = 0; mt < 4; mt++) {
                uint32_t af[4];
                const uint32_t eo =
                    (uint32_t)((wm * 64 + mt * 16 + (lane & 15)) * 40
                               + ks * 16 + ((lane >> 4) & 1) * 8) * 2;
                ldm_x4(af, sb + S2_A * 2 + eo);
#pragma unroll
                for (int p = 0; p < 2; p++)
#pragma unroll
                    for (int hf = 0; hf < 2; hf++) {
                        float* a = acc[mt][p * 2 + hf];
                        mma_f16(a, af, &wh[p][hf * 2]);
                        mma_f16(a, af, &wl[p][hf * 2]);
                    }
            }
        }
        __syncthreads();
    }
#undef ISSUE2

#pragma unroll
    for (int mt = 0; mt < 4; mt++) {
        const int rg = m0 + wm * 64 + mt * 16 + (lane >> 2);
#pragma unroll
        for (int nf = 0; nf < 4; nf++) {
            const int c = n0 + wn * 32 + nf * 8 + (lane & 3) * 2;
            const float b0 = bias[c], b1 = bias[c + 1];
            *(float2*)(C + (size_t)rg * N + c) =
                make_float2(acc[mt][nf][0] + b0, acc[mt][nf][1] + b1);
            *(float2*)(C + (size_t)(rg + 8) * N + c) =
                make_float2(acc[mt][nf][2] + b0, acc[mt][nf][3] + b1);
        }
    }
}

// ===========================================================================
// fp16 causal flash attention.
// Q exact (hi/lo), K exact (hi/lo): QK = 3 products (error ~2^-22).
// P exact (hi/lo in regs), V single: PV = 2 products.
// CTA = (128 q-rows, head, batch); 8 warps; KV tile 64 double-buffered.
// Single barrier per kv-iter.
// ===========================================================================
#define SQH 0
#define SQL 9216
#define AKV0 18432            // stage base (elements)
#define AKVSTG 13824          // per stage: KH 4608 + KL 4608 + VH 4608
#define A_KL 4608
#define A_VH 9216
#define ATTN_SMEM ((18432 + 2 * 13824) * 2)   // 92160 bytes

__global__ void __launch_bounds__(256, 2) attn_f16(
    const fp16* __restrict__ qkv_h, const fp16* __restrict__ qkv_l,
    fp16* __restrict__ oh)
{
    extern __shared__ __align__(128) char smraw[];
    const uint32_t smb = smem_u32(smraw);
    const int tid = threadIdx.x, lane = tid & 31, wid = tid >> 5;
    const int gid = lane >> 2, tig = lane & 3;
    const int bt = blockIdx.x, h = blockIdx.y, b = blockIdx.z;
    const int g0 = bt * 128;
    const int jtmax = 2 * bt + 1;

    // ---- prologue: Q (hi+lo) + KV stage 0, one group ----
    {
#pragma unroll
        for (int t = 0; t < 4; t++) {
            const int idx = tid + t * 256;
            const int row = idx >> 3;
            const int c8 = (idx & 7) * 8;
            const size_t g = ((size_t)b * SEQ + g0 + row) * K3 + h * 64 + c8;
            const uint32_t so = (uint32_t)(row * 72 + c8);
            cp16(smb + (SQH + so) * 2, qkv_h + g);
            cp16(smb + (SQL + so) * 2, qkv_l + g);
        }
#pragma unroll
        for (int t = 0; t < 2; t++) {
            const int idx = tid + t * 256;
            const int row = idx >> 3;
            const int c8 = (idx & 7) * 8;
            const size_t g = ((size_t)b * SEQ + row) * K3 + h * 64 + c8;
            const uint32_t so = AKV0 + (uint32_t)(row * 72 + c8);
            cp16(smb + so * 2, qkv_h + g + DMODEL);                  // K hi
            cp16(smb + (so + A_KL) * 2, qkv_l + g + DMODEL);         // K lo
            cp16(smb + (so + A_VH) * 2, qkv_h + g + 2 * DMODEL);     // V
        }
        asm volatile("cp.async.commit_group;");
    }

    float oacc[8][4];
#pragma unroll
    for (int i = 0; i < 8; i++)
#pragma unroll
        for (int e = 0; e < 4; e++) oacc[i][e] = 0.f;
    float mA = -CUDART_INF_F, mB = -CUDART_INF_F, lA = 0.f, lB = 0.f;

    const int wrow = g0 + wid * 16;
    const int rA = wrow + gid;

    for (int jt = 0; jt <= jtmax; jt++) {
        asm volatile("cp.async.wait_group 0;");
        __syncthreads();
        if (jt + 1 <= jtmax) {
            const int j1 = (jt + 1) * 64;
            const uint32_t stg = AKV0 + ((jt + 1) & 1) * AKVSTG;
#pragma unroll
            for (int t = 0; t < 2; t++) {
                const int idx = tid + t * 256;
                const int row = idx >> 3;
                const int c8 = (idx & 7) * 8;
                const size_t g = ((size_t)b * SEQ + j1 + row) * K3 + h * 64 + c8;
                const uint32_t so = stg + (uint32_t)(row * 72 + c8);
                cp16(smb + so * 2, qkv_h + g + DMODEL);
                cp16(smb + (so + A_KL) * 2, qkv_l + g + DMODEL);
                cp16(smb + (so + A_VH) * 2, qkv_h + g + 2 * DMODEL);
            }
            asm volatile("cp.async.commit_group;");
        }

        const uint32_t kst = AKV0 + (jt & 1) * AKVSTG;
        const int j0 = jt * 64;

        // ---- S = Q @ K^T (3 products) ----
        float sacc[8][4];
#pragma unroll
        for (int i = 0; i < 8; i++)
#pragma unroll
            for (int e = 0; e < 4; e++) sacc[i][e] = 0.f;

#pragma unroll
        for (int ks = 0; ks < 4; ks++) {
            uint32_t ah[4], al[4];
            const uint32_t eo =
                (uint32_t)((wid * 16 + (lane & 15)) * 72
                           + ks * 16 + ((lane >> 4) & 1) * 8) * 2;
            ldm_x4(ah, smb + SQH * 2 + eo);
            ldm_x4(al, smb + SQL * 2 + eo);
#pragma unroll
            for (int pf = 0; pf < 4; pf++) {
                uint32_t kh[4], kl[4];
                const uint32_t row = (uint32_t)(pf * 16 + (lane & 7)
                                                + ((lane >> 4) & 1) * 8);
                const uint32_t kc = (uint32_t)(ks * 16 + ((lane >> 3) & 1) * 8);
                const uint32_t eb = (row * 72 + kc) * 2;
                ldm_x4(kh, smb + kst * 2 + eb);
                ldm_x4(kl, smb + (kst + A_KL) * 2 + eb);
#pragma unroll
                for (int hf = 0; hf < 2; hf++) {
                    float* sa = sacc[pf * 2 + hf];
                    mma_f16(sa, ah, &kh[hf * 2]);
                    mma_f16(sa, al, &kh[hf * 2]);
                    mma_f16(sa, ah, &kl[hf * 2]);
                }
            }
        }

        // ---- scale + causal mask ----
        const bool needmask = (j0 + 63 > wrow);
#pragma unroll
        for (int nf = 0; nf < 8; nf++) {
#pragma unroll
            for (int e = 0; e < 4; e++) {
                float vsc = sacc[nf][e] * 8.0f;
                if (needmask) {
                    const int col = j0 + nf * 8 + tig * 2 + (e & 1);
                    const int row = (e < 2) ? rA : (rA + 8);
                    if (col > row) vsc = NEG_VAL;
                }
                sacc[nf][e] = vsc;
            }
        }

        // ---- online softmax ----
        float mxA = -CUDART_INF_F, mxB = -CUDART_INF_F;
#pragma unroll
        for (int nf = 0; nf < 8; nf++) {
            mxA = fmaxf(mxA, fmaxf(sacc[nf][0], sacc[nf][1]));
            mxB = fmaxf(mxB, fmaxf(sacc[nf][2], sacc[nf][3]));
        }
        mxA = fmaxf(mxA, __shfl_xor_sync(0xffffffffu, mxA, 1));
        mxA = fmaxf(mxA, __shfl_xor_sync(0xffffffffu, mxA, 2));
        mxB = fmaxf(mxB, __shfl_xor_sync(0xffffffffu, mxB, 1));
        mxB = fmaxf(mxB, __shfl_xor_sync(0xffffffffu, mxB, 2));

        const float mnA = fmaxf(mA, mxA), mnB = fmaxf(mB, mxB);
        const float alA = __expf(mA - mnA), alB = __expf(mB - mnB);

        float psA = 0.f, psB = 0.f;
        uint32_t phA[8], phB[8], plA[8], plB[8];
#pragma unroll
        for (int nf = 0; nf < 8; nf++) {
            const float p0 = __expf(sacc[nf][0] - mnA);
            const float p1 = __expf(sacc[nf][1] - mnA);
            const float p2 = __expf(sacc[nf][2] - mnB);
            const float p3 = __expf(sacc[nf][3] - mnB);
            psA += p0 + p1; psB += p2 + p3;
            fp16 h0 = __float2half_rn(p0), h1 = __float2half_rn(p1);
            fp16 h2 = __float2half_rn(p2), h3 = __float2half_rn(p3);
            phA[nf] = packh(h0, h1);
            phB[nf] = packh(h2, h3);
            plA[nf] = packh(__float2half_rn(p0 - __half2float(h0)),
                            __float2half_rn(p1 - __half2float(h1)));
            plB[nf] = packh(__float2half_rn(p2 - __half2float(h2)),
                            __float2half_rn(p3 - __half2float(h3)));
        }
        psA += __shfl_xor_sync(0xffffffffu, psA, 1);
        psA += __shfl_xor_sync(0xffffffffu, psA, 2);
        psB += __shfl_xor_sync(0xffffffffu, psB, 1);
        psB += __shfl_xor_sync(0xffffffffu, psB, 2);

        lA = lA * alA + psA; lB = lB * alB + psB;
        mA = mnA; mB = mnB;
#pragma unroll
        for (int nt = 0; nt < 8; nt++) {
            oacc[nt][0] *= alA; oacc[nt][1] *= alA;
            oacc[nt][2] *= alB; oacc[nt][3] *= alB;
        }

        // ---- O += P @ V (P exact, V single: 2 products) ----
#pragma unroll
        for (int kc = 0; kc < 4; kc++) {
            uint32_t ph[4] = { phA[2 * kc], phB[2 * kc],
                               phA[2 * kc + 1], phB[2 * kc + 1] };
            uint32_t pl[4] = { plA[2 * kc], plB[2 * kc],
                               plA[2 * kc + 1], plB[2 * kc + 1] };
#pragma unroll
            for (int ntp = 0; ntp < 4; ntp++) {
                uint32_t vh[4];
                const uint32_t ev =
                    (uint32_t)((kc * 16 + (lane & 15)) * 72
                               + ntp * 16 + ((lane >> 4) & 1) * 8) * 2;
                ldm_x4t(vh, smb + (kst + A_VH) * 2 + ev);
#pragma unroll
                for (int hf = 0; hf < 2; hf++) {
                    float* oa = oacc[ntp * 2 + hf];
                    mma_f16(oa, ph, &vh[hf * 2]);
                    mma_f16(oa, pl, &vh[hf * 2]);
                }
            }
        }
        __syncthreads();   // all warps done with buf[jt&1] before refill at jt+1
    }

    // ---- epilogue: O/l -> single fp16 ----
    const float ivA = 1.f / lA, ivB = 1.f / lB;
    const size_t gra = (size_t)b * SEQ + rA;
#pragma unroll
    for (int nt = 0; nt < 8; nt++) {
        const int col = h * 64 + nt * 8 + tig * 2;
        const float v0 = oacc[nt][0] * ivA, v1 = oacc[nt][1] * ivA;
        const float v2 = oacc[nt][2] * ivB, v3 = oacc[nt][3] * ivB;
        ((uint32_t*)oh)[(gra * DMODEL + col) >> 1] =
            packh(__float2half_rn(v0), __float2half_rn(v1));
        ((uint32_t*)oh)[((gra + 8) * DMODEL + col) >> 1] =
            packh(__float2half_rn(v2), __float2half_rn(v3));
    }
}

// ===========================================================================
extern "C" void kernel_launch(void* const* d_in, const int* in_sizes, int n_in,
                              void* d_out, int out_size)
{
    const float* q     = (const float*)d_in[0];
    const float* k     = (const float*)d_in[1];
    const float* v     = (const float*)d_in[2];
    const float* w_qkv = (const float*)d_in[3];
    const float* b_qkv = (const float*)d_in[4];
    const float* w_out = (const float*)d_in[5];
    const float* b_out = (const float*)d_in[6];
    float* out = (float*)d_out;

    fp16 *in_h, *in_l, *wqkv_h, *wqkv_l, *qkv_h, *qkv_l, *attn_h, *wout_h, *wout_l;
    cudaGetSymbolAddress((void**)&in_h,   g_in_h);
    cudaGetSymbolAddress((void**)&in_l,   g_in_l);
    cudaGetSymbolAddress((void**)&wqkv_h, g_wqkv_h);
    cudaGetSymbolAddress((void**)&wqkv_l, g_wqkv_l);
    cudaGetSymbolAddress((void**)&qkv_h,  g_qkv_h);
    cudaGetSymbolAddress((void**)&qkv_l,  g_qkv_l);
    cudaGetSymbolAddress((void**)&attn_h, g_attn_h);
    cudaGetSymbolAddress((void**)&wout_h, g_wout_h);
    cudaGetSymbolAddress((void**)&wout_l, g_wout_l);

    cudaFuncSetAttribute(gemm1_f16,
                         cudaFuncAttributeMaxDynamicSharedMemorySize, GEMM1_SMEM);
    cudaFuncSetAttribute(gemm2_f16,
                         cudaFuncAttributeMaxDynamicSharedMemorySize, GEMM2_SMEM);
    cudaFuncSetAttribute(attn_f16,
                         cudaFuncAttributeMaxDynamicSharedMemorySize, ATTN_SMEM);

    // 0) splits
    split_concat_hl<<<(MTOT * K3 / 4) / 256, 256>>>(q, k, v, in_h, in_l);
    split_w_hl<<<(K3 * K3 / 4) / 256, 256>>>(w_qkv, wqkv_h, wqkv_l);
    split_w_hl<<<(DMODEL * DMODEL / 4) / 256, 256>>>(w_out, wout_h, wout_l);

    // 1) QKV projection
    {
        dim3 g(K3 / 128, MTOT / 128);      // (24, 64)
        gemm1_f16<<<g, 256, GEMM1_SMEM>>>(in_h, in_l, wqkv_h, wqkv_l,
                                          b_qkv, qkv_h, qkv_l);
    }

    // 2) attention
    {
        dim3 g(SEQ / 128, NHEADS, BATCH);
        attn_f16<<<g, 256, ATTN_SMEM>>>(qkv_h, qkv_l, attn_h);
    }

    // 3) output projection
    {
        dim3 g(DMODEL / 128, MTOT / 128);  // (8, 64)
        gemm2_f16<<<g, 256, GEMM2_SMEM>>>(attn_h, wout_h, wout_l, b_out, out);
    }
}

// round 17
// speedup vs baseline: 1.1947x; 1.0013x over previous
#include <cuda_runtime.h>
#include <cuda_fp16.h>
#include <math_constants.h>
#include <cstdint>

#define BATCH 4
#define SEQ   2048
#define DMODEL 1024
#define NHEADS 16
#define DHEAD 64
#define NEG_VAL (-32767.0f)
#define MTOT  (BATCH * SEQ)      // 8192
#define K3    (3 * DMODEL)       // 3072

typedef __half fp16;

// ---- global scratch ----
__device__ fp16 g_in_h [(size_t)MTOT * K3];      // input hi
__device__ fp16 g_in_l [(size_t)MTOT * K3];      // input lo (exact pair)
__device__ fp16 g_wqkv_h[(size_t)K3 * K3];
__device__ fp16 g_wqkv_l[(size_t)K3 * K3];
__device__ fp16 g_qkv_h[(size_t)MTOT * K3];      // qkv hi
__device__ fp16 g_qkv_l[(size_t)MTOT * K3];      // qkv lo (q,k thirds only)
__device__ fp16 g_attn_h[(size_t)MTOT * DMODEL]; // attention out (single)
__device__ fp16 g_wout_h[(size_t)DMODEL * DMODEL];
__device__ fp16 g_wout_l[(size_t)DMODEL * DMODEL];

// ===========================================================================
// helpers
// ===========================================================================
__device__ __forceinline__ uint32_t smem_u32(const void* p) {
    uint32_t a;
    asm("{ .reg .u64 t; cvta.to.shared.u64 t, %1; cvt.u32.u64 %0, t; }"
        : "=r"(a) : "l"(p));
    return a;
}
__device__ __forceinline__ void ldm_x4(uint32_t* r, uint32_t addr) {
    asm volatile("ldmatrix.sync.aligned.m8n8.x4.shared.b16 {%0,%1,%2,%3}, [%4];"
                 : "=r"(r[0]), "=r"(r[1]), "=r"(r[2]), "=r"(r[3]) : "r"(addr));
}
__device__ __forceinline__ void ldm_x4t(uint32_t* r, uint32_t addr) {
    asm volatile("ldmatrix.sync.aligned.m8n8.x4.trans.shared.b16 {%0,%1,%2,%3}, [%4];"
                 : "=r"(r[0]), "=r"(r[1]), "=r"(r[2]), "=r"(r[3]) : "r"(addr));
}
__device__ __forceinline__ void mma_f16(float* c, const uint32_t* a, const uint32_t* b) {
    asm volatile(
        "mma.sync.aligned.m16n8k16.row.col.f32.f16.f16.f32 "
        "{%0,%1,%2,%3}, {%4,%5,%6,%7}, {%8,%9}, {%0,%1,%2,%3};"
        : "+f"(c[0]), "+f"(c[1]), "+f"(c[2]), "+f"(c[3])
        : "r"(a[0]), "r"(a[1]), "r"(a[2]), "r"(a[3]), "r"(b[0]), "r"(b[1]));
}
__device__ __forceinline__ uint32_t packh(fp16 a, fp16 b) {
    uint16_t ua = *(uint16_t*)&a, ub = *(uint16_t*)&b;
    return (uint32_t)ua | ((uint32_t)ub << 16);
}
__device__ __forceinline__ void split4h(float4 v, uint2& hi, uint2& lo) {
    fp16 hx = __float2half_rn(v.x), hy = __float2half_rn(v.y);
    fp16 hz = __float2half_rn(v.z), hw = __float2half_rn(v.w);
    fp16 lx = __float2half_rn(v.x - __half2float(hx));
    fp16 ly = __float2half_rn(v.y - __half2float(hy));
    fp16 lz = __float2half_rn(v.z - __half2float(hz));
    fp16 lw = __float2half_rn(v.w - __half2float(hw));
    hi.x = packh(hx, hy); hi.y = packh(hz, hw);
    lo.x = packh(lx, ly); lo.y = packh(lz, lw);
}
__device__ __forceinline__ void cp16(uint32_t s, const void* g) {
    asm volatile("cp.async.cg.shared.global [%0], [%1], 16;" :: "r"(s), "l"(g));
}

// ===========================================================================
// split kernels
// ===========================================================================
__global__ void __launch_bounds__(256) split_concat_hl(
    const float* __restrict__ q, const float* __restrict__ k,
    const float* __restrict__ v, fp16* __restrict__ hi, fp16* __restrict__ lo)
{
    const int idx = blockIdx.x * 256 + threadIdx.x;        // float4 index
    const int row = idx / 768;
    const int rem = idx - row * 768;
    const int seg = rem >> 8;
    const int cin = rem & 255;
    const float* src = (seg == 0) ? q : ((seg == 1) ? k : v);
    float4 val = *(const float4*)(src + (size_t)row * DMODEL + cin * 4);
    uint2 h, l;
    split4h(val, h, l);
    const size_t de = (size_t)row * K3 + rem * 4;
    *(uint2*)(hi + de) = h;
    *(uint2*)(lo + de) = l;
}

__global__ void __launch_bounds__(256) split_w_hl(
    const float* __restrict__ src, fp16* __restrict__ hi, fp16* __restrict__ lo)
{
    const size_t idx = (size_t)(blockIdx.x * 256 + threadIdx.x) * 4;
    float4 val = *(const float4*)(src + idx);
    uint2 h, l;
    split4h(val, h, l);
    *(uint2*)(hi + idx) = h;
    *(uint2*)(lo + idx) = l;
}

// ===========================================================================
// GEMM1: qkv = x @ Wqkv^T + b.  CTA 128x128, BK=32, 256 thr (2x4 warps,
// warp tile 64x32), 2-stage cp.async, 2 CTAs/SM, ONE barrier per k-iter.
// qk columns (n0<2048): 3 products AhWh+AlWh+AhWl (error ~2^-22), out hi+lo.
// v  columns (n0>=2048): 1 product AhWh (value path, 2^-11 class), out hi.
// ===========================================================================
#define S1_AH 0
#define S1_AL 5120
#define S1_WH 10240
#define S1_WL 15360
#define S1_ELEMS 20480
#define S1_BYTES (S1_ELEMS * 2)       // 40960
#define GEMM1_SMEM (2 * S1_BYTES)     // 81920

__global__ void __launch_bounds__(256, 2) gemm1_f16(
    const fp16* __restrict__ Ah, const fp16* __restrict__ Al,
    const fp16* __restrict__ Wh, const fp16* __restrict__ Wl,
    const float* __restrict__ bias,
    fp16* __restrict__ Chi, fp16* __restrict__ Clo)
{
    const int N = K3, K = K3;
    extern __shared__ __align__(128) char smraw[];
    const uint32_t smb = smem_u32(smraw);
    const int tid = threadIdx.x, lane = tid & 31, wid = tid >> 5;
    const int wm = wid & 1, wn = wid >> 1;
    const int m0 = blockIdx.y * 128, n0 = blockIdx.x * 128;
    const bool qk = (n0 < 2 * DMODEL);

    float acc[4][4][4];
#pragma unroll
    for (int i = 0; i < 4; i++)
#pragma unroll
        for (int j = 0; j < 4; j++)
#pragma unroll
            for (int e = 0; e < 4; e++) acc[i][j][e] = 0.f;

    const int nkt = K >> 5;

#define ISSUE1(sb_, k0_) do {                                                 \
    const uint32_t _sb = (sb_);                                               \
    const int _k0 = (k0_);                                                    \
    _Pragma("unroll")                                                         \
    for (int t = 0; t < 2; t++) {                                             \
        const int idx = tid + t * 256;                                        \
        const int row = idx >> 2;                                             \
        const int c8 = (idx & 3) << 3;                                        \
        const uint32_t d = (uint32_t)(row * 40 + c8) * 2;                     \
        const size_t ga = (size_t)(m0 + row) * K + _k0 + c8;                  \
        const size_t gw = (size_t)(n0 + row) * K + _k0 + c8;                  \
        cp16(_sb + S1_AH * 2 + d, Ah + ga);                                   \
        cp16(_sb + S1_WH * 2 + d, Wh + gw);                                   \
        if (qk) {                                                             \
            cp16(_sb + S1_AL * 2 + d, Al + ga);                               \
            cp16(_sb + S1_WL * 2 + d, Wl + gw);                               \
        }                                                                     \
    }                                                                         \
} while (0)

    ISSUE1(smb, 0);
    asm volatile("cp.async.commit_group;");

    for (int kt = 0; kt < nkt; kt++) {
        asm volatile("cp.async.wait_group 0;");
        __syncthreads();   // data for buf[kt&1] visible; everyone done reading buf[(kt+1)&1]
        if (kt + 1 < nkt) {
            ISSUE1(smb + ((kt + 1) & 1) * S1_BYTES, (kt + 1) << 5);
            asm volatile("cp.async.commit_group;");
        }

        const uint32_t sb = smb + (kt & 1) * S1_BYTES;
#pragma unroll
        for (int ks = 0; ks < 2; ks++) {
            uint32_t wh[2][4], wl[2][4];
#pragma unroll
            for (int p = 0; p < 2; p++) {
                const uint32_t row = (uint32_t)(wn * 32 + p * 16 + (lane & 7)
                                                + ((lane >> 4) & 1) * 8);
                const uint32_t kc = (uint32_t)(ks * 16 + ((lane >> 3) & 1) * 8);
                const uint32_t eo = (row * 40 + kc) * 2;
                ldm_x4(wh[p], sb + S1_WH * 2 + eo);
                if (qk) ldm_x4(wl[p], sb + S1_WL * 2 + eo);
            }
#pragma unroll
            for (int mt = 0; mt < 4; mt++) {
                uint32_t ah[4], al[4];
                const uint32_t eo =
                    (uint32_t)((wm * 64 + mt * 16 + (lane & 15)) * 40
                               + ks * 16 + ((lane >> 4) & 1) * 8) * 2;
                ldm_x4(ah, sb + S1_AH * 2 + eo);
                if (qk) ldm_x4(al, sb + S1_AL * 2 + eo);
#pragma unroll
                for (int p = 0; p < 2; p++)
#pragma unroll
                    for (int hf = 0; hf < 2; hf++) {
                        float* a = acc[mt][p * 2 + hf];
                        mma_f16(a, ah, &wh[p][hf * 2]);
                        if (qk) {
                            mma_f16(a, al, &wh[p][hf * 2]);
                            mma_f16(a, ah, &wl[p][hf * 2]);
                        }
                    }
            }
        }
        // no trailing barrier: next iteration's top barrier orders reads of
        // buf[kt&1] against its refill at iteration kt+2.
    }
#undef ISSUE1

    // epilogue: bias, hi always, lo for qk columns
#pragma unroll
    for (int mt = 0; mt < 4; mt++) {
        const int rg = m0 + wm * 64 + mt * 16 + (lane >> 2);
#pragma unroll
        for (int nf = 0; nf < 4; nf++) {
            const int c = n0 + wn * 32 + nf * 8 + (lane & 3) * 2;
            const float b0 = bias[c], b1 = bias[c + 1];
            const float v00 = acc[mt][nf][0] + b0, v01 = acc[mt][nf][1] + b1;
            const float v10 = acc[mt][nf][2] + b0, v11 = acc[mt][nf][3] + b1;
            fp16 h00 = __float2half_rn(v00), h01 = __float2half_rn(v01);
            fp16 h10 = __float2half_rn(v10), h11 = __float2half_rn(v11);
            ((uint32_t*)Chi)[((size_t)rg * N + c) >> 1]       = packh(h00, h01);
            ((uint32_t*)Chi)[((size_t)(rg + 8) * N + c) >> 1] = packh(h10, h11);
            if (qk) {
                fp16 l00 = __float2half_rn(v00 - __half2float(h00));
                fp16 l01 = __float2half_rn(v01 - __half2float(h01));
                fp16 l10 = __float2half_rn(v10 - __half2float(h10));
                fp16 l11 = __float2half_rn(v11 - __half2float(h11));
                ((uint32_t*)Clo)[((size_t)rg * N + c) >> 1]       = packh(l00, l01);
                ((uint32_t*)Clo)[((size_t)(rg + 8) * N + c) >> 1] = packh(l10, l11);
            }
        }
    }
}

// ===========================================================================
// GEMM2: out = attn @ (Wh+Wl)^T + b.  A single fp16, W exact: 2 products.
// fp32 output. ONE barrier per k-iter.
// ===========================================================================
#define S2_A  0
#define S2_WH 5120
#define S2_WL 10240
#define S2_ELEMS 15360
#define S2_BYTES (S2_ELEMS * 2)       // 30720
#define GEMM2_SMEM (2 * S2_BYTES)     // 61440

__global__ void __launch_bounds__(256, 2) gemm2_f16(
    const fp16* __restrict__ A, const fp16* __restrict__ Wh,
    const fp16* __restrict__ Wl, const float* __restrict__ bias,
    float* __restrict__ C)
{
    const int N = DMODEL, K = DMODEL;
    extern __shared__ __align__(128) char smraw[];
    const uint32_t smb = smem_u32(smraw);
    const int tid = threadIdx.x, lane = tid & 31, wid = tid >> 5;
    const int wm = wid & 1, wn = wid >> 1;
    const int m0 = blockIdx.y * 128, n0 = blockIdx.x * 128;

    float acc[4][4][4];
#pragma unroll
    for (int i = 0; i < 4; i++)
#pragma unroll
        for (int j = 0; j < 4; j++)
#pragma unroll
            for (int e = 0; e < 4; e++) acc[i][j][e] = 0.f;

    const int nkt = K >> 5;

#define ISSUE2(sb_, k0_) do {                                                 \
    const uint32_t _sb = (sb_);                                               \
    const int _k0 = (k0_);                                                    \
    _Pragma("unroll")                                                         \
    for (int t = 0; t < 2; t++) {                                             \
        const int idx = tid + t * 256;                                        \
        const int row = idx >> 2;                                             \
        const int c8 = (idx & 3) << 3;                                        \
        const uint32_t d = (uint32_t)(row * 40 + c8) * 2;                     \
        const size_t ga = (size_t)(m0 + row) * K + _k0 + c8;                  \
        const size_t gw = (size_t)(n0 + row) * K + _k0 + c8;                  \
        cp16(_sb + S2_A  * 2 + d, A  + ga);                                   \
        cp16(_sb + S2_WH * 2 + d, Wh + gw);                                   \
        cp16(_sb + S2_WL * 2 + d, Wl + gw);                                   \
    }                                                                         \
} while (0)

    ISSUE2(smb, 0);
    asm volatile("cp.async.commit_group;");

    for (int kt = 0; kt < nkt; kt++) {
        asm volatile("cp.async.wait_group 0;");
        __syncthreads();
        if (kt + 1 < nkt) {
            ISSUE2(smb + ((kt + 1) & 1) * S2_BYTES, (kt + 1) << 5);
            asm volatile("cp.async.commit_group;");
        }

        const uint32_t sb = smb + (kt & 1) * S2_BYTES;
#pragma unroll
        for (int ks = 0; ks < 2; ks++) {
            uint32_t wh[2][4], wl[2][4];
#pragma unroll
            for (int p = 0; p < 2; p++) {
                const uint32_t row = (uint32_t)(wn * 32 + p * 16 + (lane & 7)
                                                + ((lane >> 4) & 1) * 8);
                const uint32_t kc = (uint32_t)(ks * 16 + ((lane >> 3) & 1) * 8);
                const uint32_t eo = (row * 40 + kc) * 2;
                ldm_x4(wh[p], sb + S2_WH * 2 + eo);
                ldm_x4(wl[p], sb + S2_WL * 2 + eo);
            }
#pragma unroll
            for (int mt = 0; mt < 4; mt++) {
                uint32_t af[4];
                const uint32_t eo =
                    (uint32_t)((wm * 64 + mt * 16 + (lane & 15)) * 40
                               + ks * 16 + ((lane >> 4) & 1) * 8) * 2;
                ldm_x4(af, sb + S2_A * 2 + eo);
#pragma unroll
                for (int p = 0; p < 2; p++)
#pragma unroll
                    for (int hf = 0; hf < 2; hf++) {
                        float* a = acc[mt][p * 2 + hf];
                        mma_f16(a, af, &wh[p][hf * 2]);
                        mma_f16(a, af, &wl[p][hf * 2]);
                    }
            }
        }
        // no trailing barrier (see gemm1)
    }
#undef ISSUE2

#pragma unroll
    for (int mt = 0; mt < 4; mt++) {
        const int rg = m0 + wm * 64 + mt * 16 + (lane >> 2);
#pragma unroll
        for (int nf = 0; nf < 4; nf++) {
            const int c = n0 + wn * 32 + nf * 8 + (lane & 3) * 2;
            const float b0 = bias[c], b1 = bias[c + 1];
            *(float2*)(C + (size_t)rg * N + c) =
                make_float2(acc[mt][nf][0] + b0, acc[mt][nf][1] + b1);
            *(float2*)(C + (size_t)(rg + 8) * N + c) =
                make_float2(acc[mt][nf][2] + b0, acc[mt][nf][3] + b1);
        }
    }
}

// ===========================================================================
// fp16 causal flash attention.
// Q exact (hi/lo), K exact (hi/lo): QK = 3 products (error ~2^-22).
// P exact (hi/lo in regs), V single: PV = 2 products.
// CTA = (128 q-rows, head, batch); 8 warps; KV tile 64 double-buffered.
// ONE barrier per kv-iter.
// ===========================================================================
#define SQH 0
#define SQL 9216
#define AKV0 18432            // stage base (elements)
#define AKVSTG 13824          // per stage: KH 4608 + KL 4608 + VH 4608
#define A_KL 4608
#define A_VH 9216
#define ATTN_SMEM ((18432 + 2 * 13824) * 2)   // 92160 bytes

__global__ void __launch_bounds__(256, 2) attn_f16(
    const fp16* __restrict__ qkv_h, const fp16* __restrict__ qkv_l,
    fp16* __restrict__ oh)
{
    extern __shared__ __align__(128) char smraw[];
    const uint32_t smb = smem_u32(smraw);
    const int tid = threadIdx.x, lane = tid & 31, wid = tid >> 5;
    const int gid = lane >> 2, tig = lane & 3;
    const int bt = blockIdx.x, h = blockIdx.y, b = blockIdx.z;
    const int g0 = bt * 128;
    const int jtmax = 2 * bt + 1;

    // ---- prologue: Q (hi+lo) + KV stage 0, one group ----
    {
#pragma unroll
        for (int t = 0; t < 4; t++) {
            const int idx = tid + t * 256;
            const int row = idx >> 3;
            const int c8 = (idx & 7) * 8;
            const size_t g = ((size_t)b * SEQ + g0 + row) * K3 + h * 64 + c8;
            const uint32_t so = (uint32_t)(row * 72 + c8);
            cp16(smb + (SQH + so) * 2, qkv_h + g);
            cp16(smb + (SQL + so) * 2, qkv_l + g);
        }
#pragma unroll
        for (int t = 0; t < 2; t++) {
            const int idx = tid + t * 256;
            const int row = idx >> 3;
            const int c8 = (idx & 7) * 8;
            const size_t g = ((size_t)b * SEQ + row) * K3 + h * 64 + c8;
            const uint32_t so = AKV0 + (uint32_t)(row * 72 + c8);
            cp16(smb + so * 2, qkv_h + g + DMODEL);                  // K hi
            cp16(smb + (so + A_KL) * 2, qkv_l + g + DMODEL);         // K lo
            cp16(smb + (so + A_VH) * 2, qkv_h + g + 2 * DMODEL);     // V
        }
        asm volatile("cp.async.commit_group;");
    }

    float oacc[8][4];
#pragma unroll
    for (int i = 0; i < 8; i++)
#pragma unroll
        for (int e = 0; e < 4; e++) oacc[i][e] = 0.f;
    float mA = -CUDART_INF_F, mB = -CUDART_INF_F, lA = 0.f, lB = 0.f;

    const int wrow = g0 + wid * 16;
    const int rA = wrow + gid;

    for (int jt = 0; jt <= jtmax; jt++) {
        asm volatile("cp.async.wait_group 0;");
        __syncthreads();   // KV[jt] visible; all done reading KV[(jt+1)&1]
        if (jt + 1 <= jtmax) {
            const int j1 = (jt + 1) * 64;
            const uint32_t stg = AKV0 + ((jt + 1) & 1) * AKVSTG;
#pragma unroll
            for (int t = 0; t < 2; t++) {
                const int idx = tid + t * 256;
                const int row = idx >> 3;
                const int c8 = (idx & 7) * 8;
                const size_t g = ((size_t)b * SEQ + j1 + row) * K3 + h * 64 + c8;
                const uint32_t so = stg + (uint32_t)(row * 72 + c8);
                cp16(smb + so * 2, qkv_h + g + DMODEL);
                cp16(smb + (so + A_KL) * 2, qkv_l + g + DMODEL);
                cp16(smb + (so + A_VH) * 2, qkv_h + g + 2 * DMODEL);
            }
            asm volatile("cp.async.commit_group;");
        }

        const uint32_t kst = AKV0 + (jt & 1) * AKVSTG;
        const int j0 = jt * 64;

        // ---- S = Q @ K^T (3 products) ----
        float sacc[8][4];
#pragma unroll
        for (int i = 0; i < 8; i++)
#pragma unroll
            for (int e = 0; e < 4; e++) sacc[i][e] = 0.f;

#pragma unroll
        for (int ks = 0; ks < 4; ks++) {
            uint32_t ah[4], al[4];
            const uint32_t eo =
                (uint32_t)((wid * 16 + (lane & 15)) * 72
                           + ks * 16 + ((lane >> 4) & 1) * 8) * 2;
            ldm_x4(ah, smb + SQH * 2 + eo);
            ldm_x4(al, smb + SQL * 2 + eo);
#pragma unroll
            for (int pf = 0; pf < 4; pf++) {
                uint32_t kh[4], kl[4];
                const uint32_t row = (uint32_t)(pf * 16 + (lane & 7)
                                                + ((lane >> 4) & 1) * 8);
                const uint32_t kc = (uint32_t)(ks * 16 + ((lane >> 3) & 1) * 8);
                const uint32_t eb = (row * 72 + kc) * 2;
                ldm_x4(kh, smb + kst * 2 + eb);
                ldm_x4(kl, smb + (kst + A_KL) * 2 + eb);
#pragma unroll
                for (int hf = 0; hf < 2; hf++) {
                    float* sa = sacc[pf * 2 + hf];
                    mma_f16(sa, ah, &kh[hf * 2]);
                    mma_f16(sa, al, &kh[hf * 2]);
                    mma_f16(sa, ah, &kl[hf * 2]);
                }
            }
        }

        // ---- scale + causal mask ----
        const bool needmask = (j0 + 63 > wrow);
#pragma unroll
        for (int nf = 0; nf < 8; nf++) {
#pragma unroll
            for (int e = 0; e < 4; e++) {
                float vsc = sacc[nf][e] * 8.0f;
                if (needmask) {
                    const int col = j0 + nf * 8 + tig * 2 + (e & 1);
                    const int row = (e < 2) ? rA : (rA + 8);
                    if (col > row) vsc = NEG_VAL;
                }
                sacc[nf][e] = vsc;
            }
        }

        // ---- online softmax ----
        float mxA = -CUDART_INF_F, mxB = -CUDART_INF_F;
#pragma unroll
        for (int nf = 0; nf < 8; nf++) {
            mxA = fmaxf(mxA, fmaxf(sacc[nf][0], sacc[nf][1]));
            mxB = fmaxf(mxB, fmaxf(sacc[nf][2], sacc[nf][3]));
        }
        mxA = fmaxf(mxA, __shfl_xor_sync(0xffffffffu, mxA, 1));
        mxA = fmaxf(mxA, __shfl_xor_sync(0xffffffffu, mxA, 2));
        mxB = fmaxf(mxB, __shfl_xor_sync(0xffffffffu, mxB, 1));
        mxB = fmaxf(mxB, __shfl_xor_sync(0xffffffffu, mxB, 2));

        const float mnA = fmaxf(mA, mxA), mnB = fmaxf(mB, mxB);
        const float alA = __expf(mA - mnA), alB = __expf(mB - mnB);

        float psA = 0.f, psB = 0.f;
        uint32_t phA[8], phB[8], plA[8], plB[8];
#pragma unroll
        for (int nf = 0; nf < 8; nf++) {
            const float p0 = __expf(sacc[nf][0] - mnA);
            const float p1 = __expf(sacc[nf][1] - mnA);
            const float p2 = __expf(sacc[nf][2] - mnB);
            const float p3 = __expf(sacc[nf][3] - mnB);
            psA += p0 + p1; psB += p2 + p3;
            fp16 h0 = __float2half_rn(p0), h1 = __float2half_rn(p1);
            fp16 h2 = __float2half_rn(p2), h3 = __float2half_rn(p3);
            phA[nf] = packh(h0, h1);
            phB[nf] = packh(h2, h3);
            plA[nf] = packh(__float2half_rn(p0 - __half2float(h0)),
                            __float2half_rn(p1 - __half2float(h1)));
            plB[nf] = packh(__float2half_rn(p2 - __half2float(h2)),
                            __float2half_rn(p3 - __half2float(h3)));
        }
        psA += __shfl_xor_sync(0xffffffffu, psA, 1);
        psA += __shfl_xor_sync(0xffffffffu, psA, 2);
        psB += __shfl_xor_sync(0xffffffffu, psB, 1);
        psB += __shfl_xor_sync(0xffffffffu, psB, 2);

        lA = lA * alA + psA; lB = lB * alB + psB;
        mA = mnA; mB = mnB;
#pragma unroll
        for (int nt = 0; nt < 8; nt++) {
            oacc[nt][0] *= alA; oacc[nt][1] *= alA;
            oacc[nt][2] *= alB; oacc[nt][3] *= alB;
        }

        // ---- O += P @ V (P exact, V single: 2 products) ----
#pragma unroll
        for (int kc = 0; kc < 4; kc++) {
            uint32_t ph[4] = { phA[2 * kc], phB[2 * kc],
                               phA[2 * kc + 1], phB[2 * kc + 1] };
            uint32_t pl[4] = { plA[2 * kc], plB[2 * kc],
                               plA[2 * kc + 1], plB[2 * kc + 1] };
#pragma unroll
            for (int ntp = 0; ntp < 4; ntp++) {
                uint32_t vh[4];
                const uint32_t ev =
                    (uint32_t)((kc * 16 + (lane & 15)) * 72
                               + ntp * 16 + ((lane >> 4) & 1) * 8) * 2;
                ldm_x4t(vh, smb + (kst + A_VH) * 2 + ev);
#pragma unroll
                for (int hf = 0; hf < 2; hf++) {
                    float* oa = oacc[ntp * 2 + hf];
                    mma_f16(oa, ph, &vh[hf * 2]);
                    mma_f16(oa, pl, &vh[hf * 2]);
                }
            }
        }
        // no trailing barrier (see gemm1)
    }

    // ---- epilogue: O/l -> single fp16 ----
    const float ivA = 1.f / lA, ivB = 1.f / lB;
    const size_t gra = (size_t)b * SEQ + rA;
#pragma unroll
    for (int nt = 0; nt < 8; nt++) {
        const int col = h * 64 + nt * 8 + tig * 2;
        const float v0 = oacc[nt][0] * ivA, v1 = oacc[nt][1] * ivA;
        const float v2 = oacc[nt][2] * ivB, v3 = oacc[nt][3] * ivB;
        ((uint32_t*)oh)[(gra * DMODEL + col) >> 1] =
            packh(__float2half_rn(v0), __float2half_rn(v1));
        ((uint32_t*)oh)[((gra + 8) * DMODEL + col) >> 1] =
            packh(__float2half_rn(v2), __float2half_rn(v3));
    }
}

// ===========================================================================
extern "C" void kernel_launch(void* const* d_in, const int* in_sizes, int n_in,
                              void* d_out, int out_size)
{
    const float* q     = (const float*)d_in[0];
    const float* k     = (const float*)d_in[1];
    const float* v     = (const float*)d_in[2];
    const float* w_qkv = (const float*)d_in[3];
    const float* b_qkv = (const float*)d_in[4];
    const float* w_out = (const float*)d_in[5];
    const float* b_out = (const float*)d_in[6];
    float* out = (float*)d_out;

    fp16 *in_h, *in_l, *wqkv_h, *wqkv_l, *qkv_h, *qkv_l, *attn_h, *wout_h, *wout_l;
    cudaGetSymbolAddress((void**)&in_h,   g_in_h);
    cudaGetSymbolAddress((void**)&in_l,   g_in_l);
    cudaGetSymbolAddress((void**)&wqkv_h, g_wqkv_h);
    cudaGetSymbolAddress((void**)&wqkv_l, g_wqkv_l);
    cudaGetSymbolAddress((void**)&qkv_h,  g_qkv_h);
    cudaGetSymbolAddress((void**)&qkv_l,  g_qkv_l);
    cudaGetSymbolAddress((void**)&attn_h, g_attn_h);
    cudaGetSymbolAddress((void**)&wout_h, g_wout_h);
    cudaGetSymbolAddress((void**)&wout_l, g_wout_l);

    cudaFuncSetAttribute(gemm1_f16,
                         cudaFuncAttributeMaxDynamicSharedMemorySize, GEMM1_SMEM);
    cudaFuncSetAttribute(gemm2_f16,
                         cudaFuncAttributeMaxDynamicSharedMemorySize, GEMM2_SMEM);
    cudaFuncSetAttribute(attn_f16,
                         cudaFuncAttributeMaxDynamicSharedMemorySize, ATTN_SMEM);

    // 0) splits
    split_concat_hl<<<(MTOT * K3 / 4) / 256, 256>>>(q, k, v, in_h, in_l);
    split_w_hl<<<(K3 * K3 / 4) / 256, 256>>>(w_qkv, wqkv_h, wqkv_l);
    split_w_hl<<<(DMODEL * DMODEL / 4) / 256, 256>>>(w_out, wout_h, wout_l);

    // 1) QKV projection
    {
        dim3 g(K3 / 128, MTOT / 128);      // (24, 64)
        gemm1_f16<<<g, 256, GEMM1_SMEM>>>(in_h, in_l, wqkv_h, wqkv_l,
                                          b_qkv, qkv_h, qkv_l);
    }

    // 2) attention
    {
        dim3 g(SEQ / 128, NHEADS, BATCH);
        attn_f16<<<g, 256, ATTN_SMEM>>>(qkv_h, qkv_l, attn_h);
    }

    // 3) output projection
    {
        dim3 g(DMODEL / 128, MTOT / 128);  // (8, 64)
        gemm2_f16<<<g, 256, GEMM2_SMEM>>>(attn_h, wout_h, wout_l, b_out, out);
    }
}